// round 1
// baseline (speedup 1.0000x reference)
#include <cuda_runtime.h>
#include <math.h>
#include <float.h>

// ---------------- problem constants ----------------
constexpr int Bq = 8, Eq = 256, Nq = 32;
constexpr int Dq = 512, RDq = 768, Rq = 2000;
constexpr int Lq = 2, Kq = 8, Mq = 32, Hq = 8, DHq = 64;
constexpr int HLLMq = 4096;
constexpr int BEq = Bq * Eq;          // 2048 edge tokens
constexpr float EPSq = 1e-5f;

// ---------------- scratch (device globals; no allocs allowed) ----------------
__device__ float g_proj  [Rq * Dq];       // per-relation projected rows (4 MB, L2-resident)
__device__ float g_norm  [Rq];            // per-relation row norms
__device__ float g_states[BEq * Dq];
__device__ float g_agg   [BEq * Dq];
__device__ float g_t1    [BEq * Dq];
__device__ float g_t2    [BEq * Dq];
__device__ float g_hid   [BEq * 4 * Dq];  // 16 MB ff hidden
__device__ float g_k     [BEq * Dq];
__device__ float g_v     [BEq * Dq];
__device__ float g_q     [Mq * Dq];
__device__ float g_mem   [Bq * Mq * Dq];
__device__ float g_mem2  [Bq * Mq * Dq];
__device__ float g_noedge[Bq];            // 1.0 if batch has edges, else 0.0

// ---------------- reduction helpers ----------------
__device__ __forceinline__ float warpSum(float v) {
    #pragma unroll
    for (int o = 16; o; o >>= 1) v += __shfl_xor_sync(0xffffffffu, v, o);
    return v;
}
__device__ __forceinline__ float warpMax(float v) {
    #pragma unroll
    for (int o = 16; o; o >>= 1) v = fmaxf(v, __shfl_xor_sync(0xffffffffu, v, o));
    return v;
}
// blockDim.x must be a multiple of 32; result broadcast to all threads.
__device__ __forceinline__ float blockSum(float v, float* red) {
    int lane = threadIdx.x & 31, w = threadIdx.x >> 5;
    int nw = blockDim.x >> 5;
    v = warpSum(v);
    if (lane == 0) red[w] = v;
    __syncthreads();
    if (w == 0) {
        float r = (lane < nw) ? red[lane] : 0.f;
        r = warpSum(r);
        if (lane == 0) red[0] = r;
    }
    __syncthreads();
    float out = red[0];
    __syncthreads();
    return out;
}
__device__ __forceinline__ float blockMax(float v, float* red) {
    int lane = threadIdx.x & 31, w = threadIdx.x >> 5;
    int nw = blockDim.x >> 5;
    v = warpMax(v);
    if (lane == 0) red[w] = v;
    __syncthreads();
    if (w == 0) {
        float r = (lane < nw) ? red[lane] : -FLT_MAX;
        r = warpMax(r);
        if (lane == 0) red[0] = r;
    }
    __syncthreads();
    float out = red[0];
    __syncthreads();
    return out;
}

// ---------------- generic NT GEMM: C[M,N] = A[M,K] * W[N,K]^T + bias (+res) (+gelu) ----
// ACT: 0 = none, 1 = exact gelu. RES: add res[M,N] before activation.
// Requires K % 16 == 0 (holds for all uses: 768, 512, 2048).
template<int ACT, bool RES>
__global__ void gemm_nt(const float* __restrict__ A, const float* __restrict__ W,
                        const float* __restrict__ bias, const float* __restrict__ res,
                        float* __restrict__ C, int M, int N, int K)
{
    __shared__ float As[16][68];
    __shared__ float Ws[16][68];
    const int t  = threadIdx.x;
    const int bm = blockIdx.y * 64, bn = blockIdx.x * 64;
    const int lr = t >> 2, lk = (t & 3) * 4;      // load row / k offset
    const int ty = t >> 4, tx = t & 15;           // 16x16 compute layout, 4x4 per thread
    float acc[4][4] = {};

    for (int k0 = 0; k0 < K; k0 += 16) {
        int am = bm + lr;
        float4 av = make_float4(0.f, 0.f, 0.f, 0.f);
        if (am < M) av = *(const float4*)(A + (size_t)am * K + k0 + lk);
        As[lk + 0][lr] = av.x; As[lk + 1][lr] = av.y;
        As[lk + 2][lr] = av.z; As[lk + 3][lr] = av.w;

        int wn = bn + lr;
        float4 wv = make_float4(0.f, 0.f, 0.f, 0.f);
        if (wn < N) wv = *(const float4*)(W + (size_t)wn * K + k0 + lk);
        Ws[lk + 0][lr] = wv.x; Ws[lk + 1][lr] = wv.y;
        Ws[lk + 2][lr] = wv.z; Ws[lk + 3][lr] = wv.w;
        __syncthreads();

        #pragma unroll
        for (int kk = 0; kk < 16; kk++) {
            float4 a = *(const float4*)&As[kk][ty * 4];
            float4 b = *(const float4*)&Ws[kk][tx * 4];
            float av4[4] = {a.x, a.y, a.z, a.w};
            float bv4[4] = {b.x, b.y, b.z, b.w};
            #pragma unroll
            for (int i = 0; i < 4; i++)
                #pragma unroll
                for (int j = 0; j < 4; j++)
                    acc[i][j] += av4[i] * bv4[j];
        }
        __syncthreads();
    }

    #pragma unroll
    for (int i = 0; i < 4; i++) {
        int m = bm + ty * 4 + i;
        if (m >= M) continue;
        #pragma unroll
        for (int j = 0; j < 4; j++) {
            int n = bn + tx * 4 + j;
            if (n >= N) continue;
            float v = acc[i][j] + bias[n];
            if (RES) v += res[(size_t)m * N + n];
            if (ACT == 1) v = 0.5f * v * (1.0f + erff(v * 0.70710678118654752f));
            C[(size_t)m * N + n] = v;
        }
    }
}

// ---------------- per-relation norms ----------------
__global__ void norms_k() {
    int r = blockIdx.x, t = threadIdx.x;
    __shared__ float red[32];
    float s = 0.f;
    for (int d = t; d < Dq; d += 256) { float x = g_proj[r * Dq + d]; s += x * x; }
    s = blockSum(s, red);
    if (t == 0) g_norm[r] = fmaxf(sqrtf(s), 1e-12f);
}

// ---------------- sims + top-k + agg + states init (one block per edge) ----------------
__global__ void sims_agg_k(const int* __restrict__ eids, const int* __restrict__ nids)
{
    int be = blockIdx.x, t = threadIdx.x;
    int lane = t & 31, w = t >> 5;
    __shared__ float se[Dq];
    __shared__ float ssim[Nq];
    __shared__ int   snid[Nq];
    __shared__ int   ssel[Kq];

    int eid = eids[be];
    for (int d = t; d < Dq; d += 256) {
        float x = g_proj[eid * Dq + d];
        se[d] = x;
        g_states[(size_t)be * Dq + d] = x;     // states init = rel_vec
    }
    __syncthreads();
    float en = g_norm[eid];

    // 8 warps x 4 neighbors each: 512-dot against smem edge row
    for (int n = w; n < Nq; n += 8) {
        int nid = nids[be * Nq + n];
        float s = 0.f;
        for (int d = lane; d < Dq; d += 32) s += g_proj[nid * Dq + d] * se[d];
        s = warpSum(s);
        if (lane == 0) { snid[n] = nid; ssim[n] = s / (g_norm[nid] * en); }
    }
    __syncthreads();

    // warp 0: top-8 selection, jax tie-break (equal value -> lower index wins)
    if (w == 0) {
        float sv = ssim[lane];
        for (int it = 0; it < Kq; it++) {
            float bs = sv; int bi = lane;
            #pragma unroll
            for (int o = 16; o; o >>= 1) {
                float os = __shfl_xor_sync(0xffffffffu, bs, o);
                int   oi = __shfl_xor_sync(0xffffffffu, bi, o);
                if (os > bs || (os == bs && oi < bi)) { bs = os; bi = oi; }
            }
            if (lane == bi) sv = -FLT_MAX;      // bi identical on all lanes
            if (lane == 0) ssel[it] = snid[bi];
        }
    }
    __syncthreads();

    for (int d = t; d < Dq; d += 256) {
        float a = 0.f;
        #pragma unroll
        for (int k2 = 0; k2 < Kq; k2++) a += g_proj[ssel[k2] * Dq + d];
        g_agg[(size_t)be * Dq + d] = a * (1.0f / Kq);
    }
}

// ---------------- layernorm (optionally * edge_mask) ----------------
template<bool MASK>
__global__ void ln_k(const float* __restrict__ in, const float* __restrict__ g,
                     const float* __restrict__ b, const float* __restrict__ mask,
                     float* __restrict__ out)
{
    int be = blockIdx.x, t = threadIdx.x;
    __shared__ float red[32];
    const float* x = in + (size_t)be * Dq;
    float v0 = x[t], v1 = x[t + 256];
    float mu = blockSum(v0 + v1, red) * (1.0f / Dq);
    float d0 = v0 - mu, d1 = v1 - mu;
    float var = blockSum(d0 * d0 + d1 * d1, red) * (1.0f / Dq);
    float r = rsqrtf(var + EPSq);
    float mk = MASK ? mask[be] : 1.0f;
    out[(size_t)be * Dq + t      ] = (d0 * r * g[t      ] + b[t      ]) * mk;
    out[(size_t)be * Dq + t + 256] = (d1 * r * g[t + 256] + b[t + 256]) * mk;
}

// ---------------- no-edge flags ----------------
__global__ void noedge_k(const float* __restrict__ mask) {
    int b = blockIdx.x;
    __shared__ float red[32];
    float s = blockSum(mask[b * Eq + threadIdx.x], red);
    if (threadIdx.x == 0) g_noedge[b] = (s == 0.f) ? 0.f : 1.f;
}

// ---------------- memory-token cross attention (one block per (b,m)) ----------------
__global__ void attn_k(const float* __restrict__ mask)
{
    int bm = blockIdx.x;
    int b = bm / Mq, m = bm % Mq;
    int t = threadIdx.x;
    __shared__ float qh[DHq];
    __shared__ float sc[Eq];
    __shared__ float red[32];
    __shared__ float outp[4][DHq];

    for (int h = 0; h < Hq; h++) {
        if (t < DHq) qh[t] = g_q[m * Dq + h * DHq + t];
        __syncthreads();

        // one thread per key
        const float* kr = g_k + ((size_t)(b * Eq + t)) * Dq + h * DHq;
        float dot = 0.f;
        #pragma unroll
        for (int d = 0; d < DHq; d++) dot += qh[d] * kr[d];
        float s = dot * 0.125f;                     // 1/sqrt(64)
        if (mask[b * Eq + t] == 0.f) s = -FLT_MAX;  // finfo.min semantics

        float mx = blockMax(s, red);
        float e = expf(s - mx);                     // all-masked -> uniform, like jax
        sc[t] = e;
        float sum = blockSum(e, red);               // internal syncs publish sc[]

        // weighted V sum: 4 e-groups x 64 dims
        int d = t & 63, gpart = t >> 6;
        const float* vb0 = g_v + ((size_t)(b * Eq)) * Dq + h * DHq + d;
        float acc = 0.f;
        #pragma unroll 4
        for (int e2 = gpart * 64; e2 < gpart * 64 + 64; e2++)
            acc += sc[e2] * vb0[(size_t)e2 * Dq];
        outp[gpart][d] = acc;
        __syncthreads();
        if (t < DHq) {
            float o = (outp[0][t] + outp[1][t] + outp[2][t] + outp[3][t]) / sum;
            g_mem[(size_t)bm * Dq + h * DHq + t] = o;
        }
        __syncthreads();
    }
}

// ---------------- zero memory rows for batches with no edges ----------------
__global__ void memmask_k() {
    int i = blockIdx.x * 256 + threadIdx.x;        // over Bq*Mq*Dq = 131072
    int b = i / (Mq * Dq);
    g_mem2[i] *= g_noedge[b];
}

// ---------------- launch ----------------
extern "C" void kernel_launch(void* const* d_in, const int* in_sizes, int n_in,
                              void* d_out, int out_size)
{
    const int*   edge_ids  = (const int*)  d_in[0];
    const int*   neigh_ids = (const int*)  d_in[1];
    const float* edge_mask = (const float*)d_in[2];
    const float* rel_emb   = (const float*)d_in[3];
    const float* rp_w      = (const float*)d_in[4];
    const float* rp_b      = (const float*)d_in[5];
    const float* ly_vw     = (const float*)d_in[6];
    const float* ly_vb     = (const float*)d_in[7];
    const float* ly_ow     = (const float*)d_in[8];
    const float* ly_ob     = (const float*)d_in[9];
    const float* ly_n1g    = (const float*)d_in[10];
    const float* ly_n1b    = (const float*)d_in[11];
    const float* ly_n2g    = (const float*)d_in[12];
    const float* ly_n2b    = (const float*)d_in[13];
    const float* ly_w1     = (const float*)d_in[14];
    const float* ly_b1     = (const float*)d_in[15];
    const float* ly_w2     = (const float*)d_in[16];
    const float* ly_b2     = (const float*)d_in[17];
    const float* mem_q     = (const float*)d_in[18];
    const float* t_qw      = (const float*)d_in[19];
    const float* t_qb      = (const float*)d_in[20];
    const float* t_kw      = (const float*)d_in[21];
    const float* t_kb      = (const float*)d_in[22];
    const float* t_vw      = (const float*)d_in[23];
    const float* t_vb      = (const float*)d_in[24];
    const float* t_ow      = (const float*)d_in[25];
    const float* t_ob      = (const float*)d_in[26];
    const float* proj_w    = (const float*)d_in[27];
    const float* proj_b    = (const float*)d_in[28];
    float* out = (float*)d_out;

    float *p_proj, *p_states, *p_agg, *p_t1, *p_t2, *p_hid, *p_k, *p_v, *p_q, *p_mem, *p_mem2;
    cudaGetSymbolAddress((void**)&p_proj,   g_proj);
    cudaGetSymbolAddress((void**)&p_states, g_states);
    cudaGetSymbolAddress((void**)&p_agg,    g_agg);
    cudaGetSymbolAddress((void**)&p_t1,     g_t1);
    cudaGetSymbolAddress((void**)&p_t2,     g_t2);
    cudaGetSymbolAddress((void**)&p_hid,    g_hid);
    cudaGetSymbolAddress((void**)&p_k,      g_k);
    cudaGetSymbolAddress((void**)&p_v,      g_v);
    cudaGetSymbolAddress((void**)&p_q,      g_q);
    cudaGetSymbolAddress((void**)&p_mem,    g_mem);
    cudaGetSymbolAddress((void**)&p_mem2,   g_mem2);

    // 1) per-relation projection table: [2000,768] x [512,768]^T
    gemm_nt<0,false><<<dim3(Dq/64, (Rq + 63)/64), 256>>>(rel_emb, rp_w, rp_b, nullptr,
                                                         p_proj, Rq, Dq, RDq);
    // 2) per-relation norms
    norms_k<<<Rq, 256>>>();
    // 3) sims + top-k + agg + states init
    sims_agg_k<<<BEq, 256>>>(edge_ids, neigh_ids);

    // 4) relation-context layers
    for (int l = 0; l < Lq; l++) {
        const float* vw = ly_vw + (size_t)l * Dq * Dq;
        const float* vb = ly_vb + (size_t)l * Dq;
        const float* ow = ly_ow + (size_t)l * Dq * Dq;
        const float* ob = ly_ob + (size_t)l * Dq;
        const float* w1 = ly_w1 + (size_t)l * 4 * Dq * Dq;
        const float* b1 = ly_b1 + (size_t)l * 4 * Dq;
        const float* w2 = ly_w2 + (size_t)l * Dq * 4 * Dq;
        const float* b2 = ly_b2 + (size_t)l * Dq;

        gemm_nt<0,false><<<dim3(Dq/64, BEq/64), 256>>>(p_agg, vw, vb, nullptr,
                                                       p_t1, BEq, Dq, Dq);
        gemm_nt<0,true ><<<dim3(Dq/64, BEq/64), 256>>>(p_t1, ow, ob, p_states,
                                                       p_t2, BEq, Dq, Dq);
        ln_k<false><<<BEq, 256>>>(p_t2, ly_n1g + l*Dq, ly_n1b + l*Dq, nullptr, p_states);

        gemm_nt<1,false><<<dim3(4*Dq/64, BEq/64), 256>>>(p_states, w1, b1, nullptr,
                                                         p_hid, BEq, 4*Dq, Dq);
        gemm_nt<0,true ><<<dim3(Dq/64, BEq/64), 256>>>(p_hid, w2, b2, p_states,
                                                       p_t2, BEq, Dq, 4*Dq);
        ln_k<true><<<BEq, 256>>>(p_t2, ly_n2g + l*Dq, ly_n2b + l*Dq, edge_mask, p_states);
    }

    // 5) tokenizer projections
    gemm_nt<0,false><<<dim3(Dq/64, 1),      256>>>(mem_q,    t_qw, t_qb, nullptr, p_q,  Mq,  Dq, Dq);
    gemm_nt<0,false><<<dim3(Dq/64, BEq/64), 256>>>(p_states, t_kw, t_kb, nullptr, p_k,  BEq, Dq, Dq);
    gemm_nt<0,false><<<dim3(Dq/64, BEq/64), 256>>>(p_states, t_vw, t_vb, nullptr, p_v,  BEq, Dq, Dq);

    // 6) attention + output projection + no-edge masking
    noedge_k<<<Bq, 256>>>(edge_mask);
    attn_k<<<Bq * Mq, 256>>>(edge_mask);
    gemm_nt<0,false><<<dim3(Dq/64, (Bq*Mq)/64), 256>>>(p_mem, t_ow, t_ob, nullptr,
                                                       p_mem2, Bq*Mq, Dq, Dq);
    memmask_k<<<(Bq*Mq*Dq)/256, 256>>>();

    // 7) LLM projection -> d_out [B*M, HLLM]
    gemm_nt<0,false><<<dim3(HLLMq/64, (Bq*Mq)/64), 256>>>(p_mem2, proj_w, proj_b, nullptr,
                                                          out, Bq*Mq, HLLMq, Dq);
}

// round 3
// speedup vs baseline: 1.1867x; 1.1867x over previous
#include <cuda_runtime.h>
#include <cuda_bf16.h>
#include <math.h>
#include <float.h>
#include <stdint.h>

// ---------------- problem constants ----------------
constexpr int Bq = 8, Eq = 256, Nq = 32;
constexpr int Dq = 512, RDq = 768, Rq = 2000;
constexpr int Lq = 2, Kq = 8, Mq = 32, Hq = 8, DHq = 64;
constexpr int HLLMq = 4096;
constexpr int BEq = Bq * Eq;          // 2048 edge tokens
constexpr float EPSq = 1e-5f;

// ---------------- scratch (device globals; no allocs allowed) ----------------
__device__ float g_proj  [Rq * Dq];
__device__ float g_norm  [Rq];
__device__ float g_states[BEq * Dq];
__device__ float g_t2    [BEq * Dq];
__device__ float g_k     [BEq * Dq];
__device__ float g_v     [BEq * Dq];
__device__ float g_q     [Mq * Dq];
__device__ float g_mem2  [Bq * Mq * Dq];
__device__ float g_noedge[Bq];
// bf16 hi/lo split operand buffers
__device__ __nv_bfloat16 g_agg_h[BEq * Dq],      g_agg_l[BEq * Dq];
__device__ __nv_bfloat16 g_t1_h [BEq * Dq],      g_t1_l [BEq * Dq];
__device__ __nv_bfloat16 g_st_h [BEq * Dq],      g_st_l [BEq * Dq];
__device__ __nv_bfloat16 g_hid_h[BEq * 4 * Dq],  g_hid_l[BEq * 4 * Dq];
__device__ __nv_bfloat16 g_mem_h[Bq * Mq * Dq],  g_mem_l[Bq * Mq * Dq];
__device__ __nv_bfloat16 g_m2_h [Bq * Mq * Dq],  g_m2_l [Bq * Mq * Dq];
__device__ __nv_bfloat16 g_wh   [HLLMq * Dq],    g_wl   [HLLMq * Dq];

__device__ __forceinline__ void splitw(float v, __nv_bfloat16* H, __nv_bfloat16* L, size_t i) {
    __nv_bfloat16 h = __float2bfloat16(v);
    H[i] = h;
    L[i] = __float2bfloat16(v - __bfloat162float(h));
}

__device__ __forceinline__ uint32_t smem_u32(const void* p) {
    uint32_t a;
    asm("{ .reg .u64 t; cvta.to.shared.u64 t, %1; cvt.u32.u64 %0, t; }" : "=r"(a) : "l"(p));
    return a;
}

// ---------------- reductions ----------------
__device__ __forceinline__ float warpSum(float v) {
    #pragma unroll
    for (int o = 16; o; o >>= 1) v += __shfl_xor_sync(0xffffffffu, v, o);
    return v;
}
__device__ __forceinline__ float warpMax(float v) {
    #pragma unroll
    for (int o = 16; o; o >>= 1) v = fmaxf(v, __shfl_xor_sync(0xffffffffu, v, o));
    return v;
}
__device__ __forceinline__ float blockSum(float v, float* red) {
    int lane = threadIdx.x & 31, w = threadIdx.x >> 5;
    int nw = blockDim.x >> 5;
    v = warpSum(v);
    if (lane == 0) red[w] = v;
    __syncthreads();
    if (w == 0) {
        float r = (lane < nw) ? red[lane] : 0.f;
        r = warpSum(r);
        if (lane == 0) red[0] = r;
    }
    __syncthreads();
    float out = red[0];
    __syncthreads();
    return out;
}
__device__ __forceinline__ float blockMax(float v, float* red) {
    int lane = threadIdx.x & 31, w = threadIdx.x >> 5;
    int nw = blockDim.x >> 5;
    v = warpMax(v);
    if (lane == 0) red[w] = v;
    __syncthreads();
    if (w == 0) {
        float r = (lane < nw) ? red[lane] : -FLT_MAX;
        r = warpMax(r);
        if (lane == 0) red[0] = r;
    }
    __syncthreads();
    float out = red[0];
    __syncthreads();
    return out;
}

// ---------------- mma.sync primitives ----------------
__device__ __forceinline__ void mma16816(float* d, const uint32_t* a, const uint32_t* b) {
    asm volatile("mma.sync.aligned.m16n8k16.row.col.f32.bf16.bf16.f32 "
        "{%0,%1,%2,%3}, {%4,%5,%6,%7}, {%8,%9}, {%0,%1,%2,%3};"
        : "+f"(d[0]), "+f"(d[1]), "+f"(d[2]), "+f"(d[3])
        : "r"(a[0]), "r"(a[1]), "r"(a[2]), "r"(a[3]), "r"(b[0]), "r"(b[1]));
}
__device__ __forceinline__ void ldsm4(uint32_t& r0, uint32_t& r1, uint32_t& r2, uint32_t& r3,
                                      uint32_t addr) {
    asm volatile("ldmatrix.sync.aligned.m8n8.x4.shared.b16 {%0,%1,%2,%3}, [%4];"
        : "=r"(r0), "=r"(r1), "=r"(r2), "=r"(r3) : "r"(addr));
}
__device__ __forceinline__ void cpasync16(uint32_t dst, const void* src) {
    asm volatile("cp.async.cg.shared.global [%0], [%1], 16;\n" :: "r"(dst), "l"(src) : "memory");
}

// ================= bf16x3 NT GEMM via mma.sync =================
// C[M,N] = (Ah+Al)[M,K]*(Bh+Bl)[N,K]^T (terms AhBh+AhBl+AlBh) + bias (+res)(+gelu)
// M,N multiples of 128; K multiple of 32. Block 256 thr (8 warps, 2x4), tile 128x128, BK=32.
constexpr int PADK = 40;   // 32 + 8 bf16 pad: 80-byte row stride, ldmatrix conflict-free

template<int ACT, bool RES, bool WF32, bool WSPLIT>
__global__ __launch_bounds__(256)
void mma_nt(const __nv_bfloat16* __restrict__ Ah, const __nv_bfloat16* __restrict__ Al,
            const __nv_bfloat16* __restrict__ Bh, const __nv_bfloat16* __restrict__ Bl,
            const float* __restrict__ bias, const float* __restrict__ res,
            float* __restrict__ Cf, __nv_bfloat16* __restrict__ Ch, __nv_bfloat16* __restrict__ Cl,
            int M, int N, int K)
{
    __shared__ __nv_bfloat16 sA[2][128][PADK];
    __shared__ __nv_bfloat16 sB[2][128][PADK];

    const int tid = threadIdx.x;
    const int wid = tid >> 5, lane = tid & 31;
    const int bm = blockIdx.y * 128, bn = blockIdx.x * 128;
    const int wm = (wid >> 2) * 64, wn = (wid & 3) * 32;

    const int NI = (3 * K) / 32;

    auto load_stage = [&](int stage, int buf) {
        int c0 = stage * 32;
        int term = c0 / K;
        int kk = c0 - term * K;
        const __nv_bfloat16* As = (term < 2) ? Ah : Al;   // AhBh, AhBl, AlBh
        const __nv_bfloat16* Bs = (term == 1) ? Bl : Bh;
        uint32_t abase = smem_u32(&sA[buf][0][0]);
        uint32_t bbase = smem_u32(&sB[buf][0][0]);
        #pragma unroll
        for (int j = 0; j < 2; ++j) {
            int f = tid + 256 * j;            // 0..511
            int row = f >> 2, ch = f & 3;     // 4 x 16B chunks per 64B row
            uint32_t off = (uint32_t)(row * PADK + ch * 8) * 2;
            cpasync16(abase + off, As + (size_t)(bm + row) * K + kk + ch * 8);
            cpasync16(bbase + off, Bs + (size_t)(bn + row) * K + kk + ch * 8);
        }
        asm volatile("cp.async.commit_group;\n" ::: "memory");
    };

    float d[4][4][4];
    #pragma unroll
    for (int a = 0; a < 4; a++)
        #pragma unroll
        for (int b = 0; b < 4; b++)
            #pragma unroll
            for (int c = 0; c < 4; c++) d[a][b][c] = 0.f;

    load_stage(0, 0);
    if (NI > 1) load_stage(1, 1);

    const int a_lrow = lane & 15, a_lk = (lane >> 4) * 8;
    const int bq = lane >> 3;
    const int b_lrow = (lane & 7) + ((bq >> 1) * 8);
    const int b_lk = (bq & 1) * 8;

    for (int i = 0; i < NI; ++i) {
        if (i + 1 < NI) asm volatile("cp.async.wait_group 1;\n" ::: "memory");
        else            asm volatile("cp.async.wait_group 0;\n" ::: "memory");
        __syncthreads();

        const int buf = i & 1;
        uint32_t abase = smem_u32(&sA[buf][0][0]);
        uint32_t bbase = smem_u32(&sB[buf][0][0]);

        #pragma unroll
        for (int kh = 0; kh < 2; ++kh) {
            const int kc = kh * 16;
            uint32_t afr[4][4];
            #pragma unroll
            for (int mt = 0; mt < 4; ++mt)
                ldsm4(afr[mt][0], afr[mt][1], afr[mt][2], afr[mt][3],
                      abase + (uint32_t)((wm + mt * 16 + a_lrow) * PADK + kc + a_lk) * 2);
            uint32_t bfr[4][2];
            #pragma unroll
            for (int nt2 = 0; nt2 < 2; ++nt2) {
                uint32_t r0, r1, r2, r3;
                ldsm4(r0, r1, r2, r3,
                      bbase + (uint32_t)((wn + nt2 * 16 + b_lrow) * PADK + kc + b_lk) * 2);
                bfr[nt2 * 2][0] = r0; bfr[nt2 * 2][1] = r1;
                bfr[nt2 * 2 + 1][0] = r2; bfr[nt2 * 2 + 1][1] = r3;
            }
            #pragma unroll
            for (int mt = 0; mt < 4; ++mt)
                #pragma unroll
                for (int nt = 0; nt < 4; ++nt)
                    mma16816(d[mt][nt], afr[mt], bfr[nt]);
        }
        __syncthreads();
        if (i + 2 < NI) load_stage(i + 2, buf);
    }

    // epilogue: c-frag (m16n8 f32): regs {r0,r1}=row lane/4, cols 2*(lane&3)+{0,1}; {r2,r3}=row+8
    const int erow = lane >> 2, ecol = (lane & 3) * 2;
    #pragma unroll
    for (int mt = 0; mt < 4; ++mt) {
        #pragma unroll
        for (int h = 0; h < 2; ++h) {
            const int row = bm + wm + mt * 16 + erow + h * 8;
            #pragma unroll
            for (int nt = 0; nt < 4; ++nt) {
                const int n = bn + wn + nt * 8 + ecol;
                float v0 = d[mt][nt][h * 2 + 0];
                float v1 = d[mt][nt][h * 2 + 1];
                float2 bv = *(const float2*)(bias + n);
                v0 += bv.x; v1 += bv.y;
                if (RES) {
                    float2 rv = *(const float2*)(res + (size_t)row * N + n);
                    v0 += rv.x; v1 += rv.y;
                }
                if (ACT == 1) {
                    v0 = 0.5f * v0 * (1.0f + erff(v0 * 0.70710678118654752f));
                    v1 = 0.5f * v1 * (1.0f + erff(v1 * 0.70710678118654752f));
                }
                if (WF32)
                    *(float2*)(Cf + (size_t)row * N + n) = make_float2(v0, v1);
                if (WSPLIT) {
                    __nv_bfloat16 h0 = __float2bfloat16(v0), h1 = __float2bfloat16(v1);
                    __nv_bfloat16 l0 = __float2bfloat16(v0 - __bfloat162float(h0));
                    __nv_bfloat16 l1 = __float2bfloat16(v1 - __bfloat162float(h1));
                    uint32_t hp = ((uint32_t)__bfloat16_as_ushort(h1) << 16) | __bfloat16_as_ushort(h0);
                    uint32_t lp = ((uint32_t)__bfloat16_as_ushort(l1) << 16) | __bfloat16_as_ushort(l0);
                    *(uint32_t*)(Ch + (size_t)row * N + n) = hp;
                    *(uint32_t*)(Cl + (size_t)row * N + n) = lp;
                }
            }
        }
    }
}

// ---------------- fp32 SIMT NT GEMM (relation projection + q-proj only) ----------------
template<int ACT, bool RES>
__global__ void gemm_nt(const float* __restrict__ A, const float* __restrict__ W,
                        const float* __restrict__ bias, const float* __restrict__ res,
                        float* __restrict__ C, int M, int N, int K)
{
    __shared__ float As[16][68];
    __shared__ float Ws[16][68];
    const int t  = threadIdx.x;
    const int bm = blockIdx.y * 64, bn = blockIdx.x * 64;
    const int lr = t >> 2, lk = (t & 3) * 4;
    const int ty = t >> 4, tx = t & 15;
    float acc[4][4] = {};

    for (int k0 = 0; k0 < K; k0 += 16) {
        int am = bm + lr;
        float4 av = make_float4(0.f, 0.f, 0.f, 0.f);
        if (am < M) av = *(const float4*)(A + (size_t)am * K + k0 + lk);
        As[lk + 0][lr] = av.x; As[lk + 1][lr] = av.y;
        As[lk + 2][lr] = av.z; As[lk + 3][lr] = av.w;
        int wn = bn + lr;
        float4 wv = make_float4(0.f, 0.f, 0.f, 0.f);
        if (wn < N) wv = *(const float4*)(W + (size_t)wn * K + k0 + lk);
        Ws[lk + 0][lr] = wv.x; Ws[lk + 1][lr] = wv.y;
        Ws[lk + 2][lr] = wv.z; Ws[lk + 3][lr] = wv.w;
        __syncthreads();
        #pragma unroll
        for (int kk = 0; kk < 16; kk++) {
            float4 a = *(const float4*)&As[kk][ty * 4];
            float4 b = *(const float4*)&Ws[kk][tx * 4];
            float av4[4] = {a.x, a.y, a.z, a.w};
            float bv4[4] = {b.x, b.y, b.z, b.w};
            #pragma unroll
            for (int i = 0; i < 4; i++)
                #pragma unroll
                for (int j = 0; j < 4; j++)
                    acc[i][j] += av4[i] * bv4[j];
        }
        __syncthreads();
    }
    #pragma unroll
    for (int i = 0; i < 4; i++) {
        int m = bm + ty * 4 + i;
        if (m >= M) continue;
        #pragma unroll
        for (int j = 0; j < 4; j++) {
            int n = bn + tx * 4 + j;
            if (n >= N) continue;
            float v = acc[i][j] + bias[n];
            if (RES) v += res[(size_t)m * N + n];
            if (ACT == 1) v = 0.5f * v * (1.0f + erff(v * 0.70710678118654752f));
            C[(size_t)m * N + n] = v;
        }
    }
}

// ---------------- weight hi/lo split ----------------
__global__ void split_k(const float* __restrict__ x, __nv_bfloat16* __restrict__ h,
                        __nv_bfloat16* __restrict__ l, int n)
{
    int i = blockIdx.x * 256 + threadIdx.x;
    if (i < n) splitw(x[i], h, l, i);
}

// ---------------- per-relation norms ----------------
__global__ void norms_k() {
    int r = blockIdx.x, t = threadIdx.x;
    __shared__ float red[32];
    float s = 0.f;
    for (int d = t; d < Dq; d += 256) { float x = g_proj[r * Dq + d]; s += x * x; }
    s = blockSum(s, red);
    if (t == 0) g_norm[r] = fmaxf(sqrtf(s), 1e-12f);
}

// ---------------- sims + top-k + agg(split) + states init ----------------
__global__ void sims_agg_k(const int* __restrict__ eids, const int* __restrict__ nids)
{
    int be = blockIdx.x, t = threadIdx.x;
    int lane = t & 31, w = t >> 5;
    __shared__ float se[Dq];
    __shared__ float ssim[Nq];
    __shared__ int   snid[Nq];
    __shared__ int   ssel[Kq];

    int eid = eids[be];
    for (int d = t; d < Dq; d += 256) {
        float x = g_proj[eid * Dq + d];
        se[d] = x;
        g_states[(size_t)be * Dq + d] = x;
    }
    __syncthreads();
    float en = g_norm[eid];

    for (int n = w; n < Nq; n += 8) {
        int nid = nids[be * Nq + n];
        float s = 0.f;
        for (int d = lane; d < Dq; d += 32) s += g_proj[nid * Dq + d] * se[d];
        s = warpSum(s);
        if (lane == 0) { snid[n] = nid; ssim[n] = s / (g_norm[nid] * en); }
    }
    __syncthreads();

    if (w == 0) {
        float sv = ssim[lane];
        for (int it = 0; it < Kq; it++) {
            float bs = sv; int bi = lane;
            #pragma unroll
            for (int o = 16; o; o >>= 1) {
                float os = __shfl_xor_sync(0xffffffffu, bs, o);
                int   oi = __shfl_xor_sync(0xffffffffu, bi, o);
                if (os > bs || (os == bs && oi < bi)) { bs = os; bi = oi; }
            }
            if (lane == bi) sv = -FLT_MAX;
            if (lane == 0) ssel[it] = snid[bi];
        }
    }
    __syncthreads();

    for (int d = t; d < Dq; d += 256) {
        float a = 0.f;
        #pragma unroll
        for (int k2 = 0; k2 < Kq; k2++) a += g_proj[ssel[k2] * Dq + d];
        splitw(a * (1.0f / Kq), g_agg_h, g_agg_l, (size_t)be * Dq + d);
    }
}

// ---------------- layernorm -> fp32 states + hi/lo split ----------------
template<bool MASK>
__global__ void ln_k(const float* __restrict__ in, const float* __restrict__ g,
                     const float* __restrict__ b, const float* __restrict__ mask,
                     float* __restrict__ out, __nv_bfloat16* __restrict__ oh,
                     __nv_bfloat16* __restrict__ ol)
{
    int be = blockIdx.x, t = threadIdx.x;
    __shared__ float red[32];
    const float* x = in + (size_t)be * Dq;
    float v0 = x[t], v1 = x[t + 256];
    float mu = blockSum(v0 + v1, red) * (1.0f / Dq);
    float d0 = v0 - mu, d1 = v1 - mu;
    float var = blockSum(d0 * d0 + d1 * d1, red) * (1.0f / Dq);
    float r = rsqrtf(var + EPSq);
    float mk = MASK ? mask[be] : 1.0f;
    float o0 = (d0 * r * g[t      ] + b[t      ]) * mk;
    float o1 = (d1 * r * g[t + 256] + b[t + 256]) * mk;
    size_t i0 = (size_t)be * Dq + t, i1 = i0 + 256;
    out[i0] = o0; out[i1] = o1;
    splitw(o0, oh, ol, i0);
    splitw(o1, oh, ol, i1);
}

// ---------------- no-edge flags ----------------
__global__ void noedge_k(const float* __restrict__ mask) {
    int b = blockIdx.x;
    __shared__ float red[32];
    float s = blockSum(mask[b * Eq + threadIdx.x], red);
    if (threadIdx.x == 0) g_noedge[b] = (s == 0.f) ? 0.f : 1.f;
}

// ---------------- memory-token cross attention (out: mem hi/lo) ----------------
__global__ void attn_k(const float* __restrict__ mask)
{
    int bm = blockIdx.x;
    int b = bm / Mq, m = bm % Mq;
    int t = threadIdx.x;
    __shared__ float qh[DHq];
    __shared__ float sc[Eq];
    __shared__ float red[32];
    __shared__ float outp[4][DHq];

    for (int h = 0; h < Hq; h++) {
        if (t < DHq) qh[t] = g_q[m * Dq + h * DHq + t];
        __syncthreads();

        const float* kr = g_k + ((size_t)(b * Eq + t)) * Dq + h * DHq;
        float dot = 0.f;
        #pragma unroll
        for (int d = 0; d < DHq; d++) dot += qh[d] * kr[d];
        float s = dot * 0.125f;
        if (mask[b * Eq + t] == 0.f) s = -FLT_MAX;

        float mx = blockMax(s, red);
        float e = expf(s - mx);
        sc[t] = e;
        float sum = blockSum(e, red);

        int d = t & 63, gpart = t >> 6;
        const float* vb0 = g_v + ((size_t)(b * Eq)) * Dq + h * DHq + d;
        float acc = 0.f;
        #pragma unroll 4
        for (int e2 = gpart * 64; e2 < gpart * 64 + 64; e2++)
            acc += sc[e2] * vb0[(size_t)e2 * Dq];
        outp[gpart][d] = acc;
        __syncthreads();
        if (t < DHq) {
            float o = (outp[0][t] + outp[1][t] + outp[2][t] + outp[3][t]) / sum;
            splitw(o, g_mem_h, g_mem_l, (size_t)bm * Dq + h * DHq + t);
        }
        __syncthreads();
    }
}

// ---------------- no-edge mask + split for final proj ----------------
__global__ void memmask_k() {
    int i = blockIdx.x * 256 + threadIdx.x;       // Bq*Mq*Dq = 131072
    int b = i / (Mq * Dq);
    splitw(g_mem2[i] * g_noedge[b], g_m2_h, g_m2_l, i);
}

// ---------------- launch ----------------
extern "C" void kernel_launch(void* const* d_in, const int* in_sizes, int n_in,
                              void* d_out, int out_size)
{
    const int*   edge_ids  = (const int*)  d_in[0];
    const int*   neigh_ids = (const int*)  d_in[1];
    const float* edge_mask = (const float*)d_in[2];
    const float* rel_emb   = (const float*)d_in[3];
    const float* rp_w      = (const float*)d_in[4];
    const float* rp_b      = (const float*)d_in[5];
    const float* ly_vw     = (const float*)d_in[6];
    const float* ly_vb     = (const float*)d_in[7];
    const float* ly_ow     = (const float*)d_in[8];
    const float* ly_ob     = (const float*)d_in[9];
    const float* ly_n1g    = (const float*)d_in[10];
    const float* ly_n1b    = (const float*)d_in[11];
    const float* ly_n2g    = (const float*)d_in[12];
    const float* ly_n2b    = (const float*)d_in[13];
    const float* ly_w1     = (const float*)d_in[14];
    const float* ly_b1     = (const float*)d_in[15];
    const float* ly_w2     = (const float*)d_in[16];
    const float* ly_b2     = (const float*)d_in[17];
    const float* mem_q     = (const float*)d_in[18];
    const float* t_qw      = (const float*)d_in[19];
    const float* t_qb      = (const float*)d_in[20];
    const float* t_kw      = (const float*)d_in[21];
    const float* t_kb      = (const float*)d_in[22];
    const float* t_vw      = (const float*)d_in[23];
    const float* t_vb      = (const float*)d_in[24];
    const float* t_ow      = (const float*)d_in[25];
    const float* t_ob      = (const float*)d_in[26];
    const float* proj_w    = (const float*)d_in[27];
    const float* proj_b    = (const float*)d_in[28];
    float* out = (float*)d_out;

    float *p_proj, *p_states, *p_t2, *p_k, *p_v, *p_q, *p_mem2;
    __nv_bfloat16 *p_agg_h, *p_agg_l, *p_t1_h, *p_t1_l, *p_st_h, *p_st_l;
    __nv_bfloat16 *p_hid_h, *p_hid_l, *p_mem_h, *p_mem_l, *p_m2_h, *p_m2_l, *p_wh, *p_wl;
    cudaGetSymbolAddress((void**)&p_proj,   g_proj);
    cudaGetSymbolAddress((void**)&p_states, g_states);
    cudaGetSymbolAddress((void**)&p_t2,     g_t2);
    cudaGetSymbolAddress((void**)&p_k,      g_k);
    cudaGetSymbolAddress((void**)&p_v,      g_v);
    cudaGetSymbolAddress((void**)&p_q,      g_q);
    cudaGetSymbolAddress((void**)&p_mem2,   g_mem2);
    cudaGetSymbolAddress((void**)&p_agg_h,  g_agg_h);
    cudaGetSymbolAddress((void**)&p_agg_l,  g_agg_l);
    cudaGetSymbolAddress((void**)&p_t1_h,   g_t1_h);
    cudaGetSymbolAddress((void**)&p_t1_l,   g_t1_l);
    cudaGetSymbolAddress((void**)&p_st_h,   g_st_h);
    cudaGetSymbolAddress((void**)&p_st_l,   g_st_l);
    cudaGetSymbolAddress((void**)&p_hid_h,  g_hid_h);
    cudaGetSymbolAddress((void**)&p_hid_l,  g_hid_l);
    cudaGetSymbolAddress((void**)&p_mem_h,  g_mem_h);
    cudaGetSymbolAddress((void**)&p_mem_l,  g_mem_l);
    cudaGetSymbolAddress((void**)&p_m2_h,   g_m2_h);
    cudaGetSymbolAddress((void**)&p_m2_l,   g_m2_l);
    cudaGetSymbolAddress((void**)&p_wh,     g_wh);
    cudaGetSymbolAddress((void**)&p_wl,     g_wl);

    // 1) relation projection (fp32 SIMT — feeds discrete top-k, must stay fp32)
    gemm_nt<0,false><<<dim3(Dq/64, (Rq + 63)/64), 256>>>(rel_emb, rp_w, rp_b, nullptr,
                                                         p_proj, Rq, Dq, RDq);
    norms_k<<<Rq, 256>>>();
    sims_agg_k<<<BEq, 256>>>(edge_ids, neigh_ids);

    // 2) relation-context layers (mma.sync bf16x3)
    for (int l = 0; l < Lq; l++) {
        const float* vw = ly_vw + (size_t)l * Dq * Dq;
        const float* ow = ly_ow + (size_t)l * Dq * Dq;
        const float* w1 = ly_w1 + (size_t)l * 4 * Dq * Dq;
        const float* w2 = ly_w2 + (size_t)l * Dq * 4 * Dq;

        split_k<<<(Dq*Dq)/256, 256>>>(vw, p_wh, p_wl, Dq*Dq);
        mma_nt<0,false,false,true><<<dim3(Dq/128, BEq/128), 256>>>(
            p_agg_h, p_agg_l, p_wh, p_wl, ly_vb + l*Dq, nullptr,
            nullptr, p_t1_h, p_t1_l, BEq, Dq, Dq);

        split_k<<<(Dq*Dq)/256, 256>>>(ow, p_wh, p_wl, Dq*Dq);
        mma_nt<0,true,true,false><<<dim3(Dq/128, BEq/128), 256>>>(
            p_t1_h, p_t1_l, p_wh, p_wl, ly_ob + l*Dq, p_states,
            p_t2, nullptr, nullptr, BEq, Dq, Dq);
        ln_k<false><<<BEq, 256>>>(p_t2, ly_n1g + l*Dq, ly_n1b + l*Dq, nullptr,
                                  p_states, p_st_h, p_st_l);

        split_k<<<(4*Dq*Dq)/256, 256>>>(w1, p_wh, p_wl, 4*Dq*Dq);
        mma_nt<1,false,false,true><<<dim3(4*Dq/128, BEq/128), 256>>>(
            p_st_h, p_st_l, p_wh, p_wl, ly_b1 + l*4*Dq, nullptr,
            nullptr, p_hid_h, p_hid_l, BEq, 4*Dq, Dq);

        split_k<<<(4*Dq*Dq)/256, 256>>>(w2, p_wh, p_wl, 4*Dq*Dq);
        mma_nt<0,true,true,false><<<dim3(Dq/128, BEq/128), 256>>>(
            p_hid_h, p_hid_l, p_wh, p_wl, ly_b2 + l*Dq, p_states,
            p_t2, nullptr, nullptr, BEq, Dq, 4*Dq);
        ln_k<true><<<BEq, 256>>>(p_t2, ly_n2g + l*Dq, ly_n2b + l*Dq, edge_mask,
                                 p_states, p_st_h, p_st_l);
    }

    // 3) tokenizer projections
    gemm_nt<0,false><<<dim3(Dq/64, 1), 256>>>(mem_q, t_qw, t_qb, nullptr, p_q, Mq, Dq, Dq);
    split_k<<<(Dq*Dq)/256, 256>>>(t_kw, p_wh, p_wl, Dq*Dq);
    mma_nt<0,false,true,false><<<dim3(Dq/128, BEq/128), 256>>>(
        p_st_h, p_st_l, p_wh, p_wl, t_kb, nullptr, p_k, nullptr, nullptr, BEq, Dq, Dq);
    split_k<<<(Dq*Dq)/256, 256>>>(t_vw, p_wh, p_wl, Dq*Dq);
    mma_nt<0,false,true,false><<<dim3(Dq/128, BEq/128), 256>>>(
        p_st_h, p_st_l, p_wh, p_wl, t_vb, nullptr, p_v, nullptr, nullptr, BEq, Dq, Dq);

    // 4) attention + output proj + no-edge masking
    noedge_k<<<Bq, 256>>>(edge_mask);
    attn_k<<<Bq * Mq, 256>>>(edge_mask);
    split_k<<<(Dq*Dq)/256, 256>>>(t_ow, p_wh, p_wl, Dq*Dq);
    mma_nt<0,false,true,false><<<dim3(Dq/128, (Bq*Mq)/128), 256>>>(
        p_mem_h, p_mem_l, p_wh, p_wl, t_ob, nullptr, p_mem2, nullptr, nullptr, Bq*Mq, Dq, Dq);
    memmask_k<<<(Bq*Mq*Dq)/256, 256>>>();

    // 5) LLM projection -> d_out
    split_k<<<(HLLMq*Dq)/256, 256>>>(proj_w, p_wh, p_wl, HLLMq*Dq);
    mma_nt<0,false,true,false><<<dim3(HLLMq/128, (Bq*Mq)/128), 256>>>(
        p_m2_h, p_m2_l, p_wh, p_wl, proj_b, nullptr, out, nullptr, nullptr, Bq*Mq, HLLMq, Dq);
}

// round 4
// speedup vs baseline: 1.4118x; 1.1897x over previous
#include <cuda_runtime.h>
#include <cuda_bf16.h>
#include <math.h>
#include <float.h>
#include <stdint.h>

// ---------------- problem constants ----------------
constexpr int Bq = 8, Eq = 256, Nq = 32;
constexpr int Dq = 512, RDq = 768, Rq = 2000;
constexpr int Lq = 2, Kq = 8, Mq = 32, Hq = 8, DHq = 64;
constexpr int HLLMq = 4096;
constexpr int BEq = Bq * Eq;          // 2048 edge tokens
constexpr float EPSq = 1e-5f;

// ---------------- scratch (device globals; no allocs allowed) ----------------
__device__ float g_proj  [Rq * Dq];
__device__ float g_norm  [Rq];
__device__ float g_states[BEq * Dq];
__device__ float g_t2    [BEq * Dq];
__device__ float g_k     [BEq * Dq];
__device__ float g_v     [BEq * Dq];
__device__ float g_q     [Mq * Dq];
__device__ float g_mem2  [Bq * Mq * Dq];
__device__ float g_noedge[Bq];
// bf16 hi/lo split activation buffers
__device__ __align__(256) __nv_bfloat16 g_agg_h[BEq * Dq],      g_agg_l[BEq * Dq];
__device__ __align__(256) __nv_bfloat16 g_t1_h [BEq * Dq],      g_t1_l [BEq * Dq];
__device__ __align__(256) __nv_bfloat16 g_st_h [BEq * Dq],      g_st_l [BEq * Dq];
__device__ __align__(256) __nv_bfloat16 g_hid_h[BEq * 4 * Dq],  g_hid_l[BEq * 4 * Dq];
__device__ __align__(256) __nv_bfloat16 g_mem_h[Bq * Mq * Dq],  g_mem_l[Bq * Mq * Dq];
__device__ __align__(256) __nv_bfloat16 g_m2_h [Bq * Mq * Dq],  g_m2_l [Bq * Mq * Dq];
// bf16 hi/lo split weight buffers (all live simultaneously; one fused split pass)
__device__ __align__(256) __nv_bfloat16 g_wv_h[Lq][Dq * Dq],     g_wv_l[Lq][Dq * Dq];
__device__ __align__(256) __nv_bfloat16 g_wo_h[Lq][Dq * Dq],     g_wo_l[Lq][Dq * Dq];
__device__ __align__(256) __nv_bfloat16 g_w1_h[Lq][4 * Dq * Dq], g_w1_l[Lq][4 * Dq * Dq];
__device__ __align__(256) __nv_bfloat16 g_w2_h[Lq][4 * Dq * Dq], g_w2_l[Lq][4 * Dq * Dq];
__device__ __align__(256) __nv_bfloat16 g_tk_h[Dq * Dq],         g_tk_l[Dq * Dq];
__device__ __align__(256) __nv_bfloat16 g_tv_h[Dq * Dq],         g_tv_l[Dq * Dq];
__device__ __align__(256) __nv_bfloat16 g_to_h[Dq * Dq],         g_to_l[Dq * Dq];
__device__ __align__(256) __nv_bfloat16 g_pw_h[HLLMq * Dq],      g_pw_l[HLLMq * Dq];

__device__ __forceinline__ void splitw(float v, __nv_bfloat16* H, __nv_bfloat16* L, size_t i) {
    __nv_bfloat16 h = __float2bfloat16(v);
    H[i] = h;
    L[i] = __float2bfloat16(v - __bfloat162float(h));
}

__device__ __forceinline__ uint32_t smem_u32(const void* p) {
    uint32_t a;
    asm("{ .reg .u64 t; cvta.to.shared.u64 t, %1; cvt.u32.u64 %0, t; }" : "=r"(a) : "l"(p));
    return a;
}

// ---------------- reductions ----------------
__device__ __forceinline__ float warpSum(float v) {
    #pragma unroll
    for (int o = 16; o; o >>= 1) v += __shfl_xor_sync(0xffffffffu, v, o);
    return v;
}
__device__ __forceinline__ float warpMax(float v) {
    #pragma unroll
    for (int o = 16; o; o >>= 1) v = fmaxf(v, __shfl_xor_sync(0xffffffffu, v, o));
    return v;
}
__device__ __forceinline__ float blockSum(float v, float* red) {
    int lane = threadIdx.x & 31, w = threadIdx.x >> 5;
    int nw = blockDim.x >> 5;
    v = warpSum(v);
    if (lane == 0) red[w] = v;
    __syncthreads();
    if (w == 0) {
        float r = (lane < nw) ? red[lane] : 0.f;
        r = warpSum(r);
        if (lane == 0) red[0] = r;
    }
    __syncthreads();
    float out = red[0];
    __syncthreads();
    return out;
}
__device__ __forceinline__ float blockMax(float v, float* red) {
    int lane = threadIdx.x & 31, w = threadIdx.x >> 5;
    int nw = blockDim.x >> 5;
    v = warpMax(v);
    if (lane == 0) red[w] = v;
    __syncthreads();
    if (w == 0) {
        float r = (lane < nw) ? red[lane] : -FLT_MAX;
        r = warpMax(r);
        if (lane == 0) red[0] = r;
    }
    __syncthreads();
    float out = red[0];
    __syncthreads();
    return out;
}

// ---------------- mma.sync primitives (proven in R3) ----------------
__device__ __forceinline__ void mma16816(float* d, const uint32_t* a, const uint32_t* b) {
    asm volatile("mma.sync.aligned.m16n8k16.row.col.f32.bf16.bf16.f32 "
        "{%0,%1,%2,%3}, {%4,%5,%6,%7}, {%8,%9}, {%0,%1,%2,%3};"
        : "+f"(d[0]), "+f"(d[1]), "+f"(d[2]), "+f"(d[3])
        : "r"(a[0]), "r"(a[1]), "r"(a[2]), "r"(a[3]), "r"(b[0]), "r"(b[1]));
}
__device__ __forceinline__ void ldsm4(uint32_t& r0, uint32_t& r1, uint32_t& r2, uint32_t& r3,
                                      uint32_t addr) {
    asm volatile("ldmatrix.sync.aligned.m8n8.x4.shared.b16 {%0,%1,%2,%3}, [%4];"
        : "=r"(r0), "=r"(r1), "=r"(r2), "=r"(r3) : "r"(addr));
}
__device__ __forceinline__ void cpasync16(uint32_t dst, const void* src) {
    asm volatile("cp.async.cg.shared.global [%0], [%1], 16;\n" :: "r"(dst), "l"(src) : "memory");
}

// ================= bf16x3 NT GEMM via mma.sync, 4-stage pipeline =================
// C[M,N] = (Ah+Al)[M,K]*(Bh+Bl)[N,K]^T (terms AhBh+AhBl+AlBh) + bias (+res)(+gelu)
// M % TM == 0, N % TN == 0, K % 32 == 0, 3K/32 >= 3. 256 threads.
constexpr int PADK = 40;   // 80-byte row stride: 16B-aligned & ldmatrix conflict-free
constexpr int NSTG = 4;

template<int TM, int TN, int WR, int WC, int ACT, bool RES, bool WF32, bool WSPLIT>
__global__ __launch_bounds__(256)
void mma_nt(const __nv_bfloat16* __restrict__ Ah, const __nv_bfloat16* __restrict__ Al,
            const __nv_bfloat16* __restrict__ Bh, const __nv_bfloat16* __restrict__ Bl,
            const float* __restrict__ bias, const float* __restrict__ res,
            float* __restrict__ Cf, __nv_bfloat16* __restrict__ Ch, __nv_bfloat16* __restrict__ Cl,
            int M, int N, int K)
{
    extern __shared__ __align__(128) __nv_bfloat16 smem[];
    constexpr int STG_E = (TM + TN) * PADK;       // elems per stage
    constexpr int tm = TM / WR, tn = TN / WC;
    constexpr int MT = tm / 16, NT = tn / 8;

    const int tid = threadIdx.x;
    const int wid = tid >> 5, lane = tid & 31;
    const int bm = blockIdx.y * TM, bn = blockIdx.x * TN;
    const int wm = (wid / WC) * tm, wn = (wid % WC) * tn;
    const uint32_t sbase = smem_u32(smem);

    const int NI = (3 * K) / 32;

    auto load_stage = [&](int stage, int buf) {
        int c0 = stage * 32;
        int term = c0 / K;
        int kk = c0 - term * K;
        const __nv_bfloat16* As = (term < 2) ? Ah : Al;   // AhBh, AhBl, AlBh
        const __nv_bfloat16* Bs = (term == 1) ? Bl : Bh;
        uint32_t base = sbase + (uint32_t)buf * STG_E * 2;
        constexpr int CHA = TM * 4, CH = (TM + TN) * 4;
        #pragma unroll
        for (int j = 0; j < CH / 256; ++j) {
            int f = tid + 256 * j;
            if (f < CHA) {
                int row = f >> 2, ch = f & 3;
                cpasync16(base + (uint32_t)(row * PADK + ch * 8) * 2,
                          As + (size_t)(bm + row) * K + kk + ch * 8);
            } else {
                int f2 = f - CHA;
                int row = f2 >> 2, ch = f2 & 3;
                cpasync16(base + (uint32_t)(TM * PADK + row * PADK + ch * 8) * 2,
                          Bs + (size_t)(bn + row) * K + kk + ch * 8);
            }
        }
        asm volatile("cp.async.commit_group;\n" ::: "memory");
    };

    float d[MT][NT][4];
    #pragma unroll
    for (int a = 0; a < MT; a++)
        #pragma unroll
        for (int b = 0; b < NT; b++)
            #pragma unroll
            for (int c = 0; c < 4; c++) d[a][b][c] = 0.f;

    load_stage(0, 0);
    load_stage(1, 1);
    load_stage(2, 2);

    const int a_lrow = lane & 15, a_lk = (lane >> 4) * 8;
    const int bq = lane >> 3;
    const int b_lrow = (lane & 7) + ((bq >> 1) * 8);
    const int b_lk = (bq & 1) * 8;

    for (int i = 0; i < NI; ++i) {
        // commits issued so far = min(i+3, NI); need stage i complete
        if (i + 3 <= NI)      asm volatile("cp.async.wait_group 2;\n" ::: "memory");
        else if (i + 2 == NI) asm volatile("cp.async.wait_group 1;\n" ::: "memory");
        else                  asm volatile("cp.async.wait_group 0;\n" ::: "memory");
        __syncthreads();   // data visible + all warps done with stage i-1 (buf (i+3)%4)

        if (i + 3 < NI) load_stage(i + 3, (i + 3) & (NSTG - 1));

        const uint32_t abase = sbase + (uint32_t)(i & (NSTG - 1)) * STG_E * 2;
        const uint32_t bbase = abase + TM * PADK * 2;

        #pragma unroll
        for (int kh = 0; kh < 2; ++kh) {
            const int kc = kh * 16;
            uint32_t afr[MT][4];
            #pragma unroll
            for (int mt = 0; mt < MT; ++mt)
                ldsm4(afr[mt][0], afr[mt][1], afr[mt][2], afr[mt][3],
                      abase + (uint32_t)((wm + mt * 16 + a_lrow) * PADK + kc + a_lk) * 2);
            uint32_t bfr[NT][2];
            #pragma unroll
            for (int nt2 = 0; nt2 < NT / 2; ++nt2) {
                uint32_t r0, r1, r2, r3;
                ldsm4(r0, r1, r2, r3,
                      bbase + (uint32_t)((wn + nt2 * 16 + b_lrow) * PADK + kc + b_lk) * 2);
                bfr[nt2 * 2][0] = r0; bfr[nt2 * 2][1] = r1;
                bfr[nt2 * 2 + 1][0] = r2; bfr[nt2 * 2 + 1][1] = r3;
            }
            #pragma unroll
            for (int mt = 0; mt < MT; ++mt)
                #pragma unroll
                for (int nt = 0; nt < NT; ++nt)
                    mma16816(d[mt][nt], afr[mt], bfr[nt]);
        }
    }

    // epilogue: c-frag rows lane/4 (+8), cols 2*(lane&3)+{0,1}
    const int erow = lane >> 2, ecol = (lane & 3) * 2;
    #pragma unroll
    for (int mt = 0; mt < MT; ++mt) {
        #pragma unroll
        for (int h = 0; h < 2; ++h) {
            const int row = bm + wm + mt * 16 + erow + h * 8;
            #pragma unroll
            for (int nt = 0; nt < NT; ++nt) {
                const int n = bn + wn + nt * 8 + ecol;
                float v0 = d[mt][nt][h * 2 + 0];
                float v1 = d[mt][nt][h * 2 + 1];
                float2 bv = *(const float2*)(bias + n);
                v0 += bv.x; v1 += bv.y;
                if (RES) {
                    float2 rv = *(const float2*)(res + (size_t)row * N + n);
                    v0 += rv.x; v1 += rv.y;
                }
                if (ACT == 1) {
                    v0 = 0.5f * v0 * (1.0f + erff(v0 * 0.70710678118654752f));
                    v1 = 0.5f * v1 * (1.0f + erff(v1 * 0.70710678118654752f));
                }
                if (WF32)
                    *(float2*)(Cf + (size_t)row * N + n) = make_float2(v0, v1);
                if (WSPLIT) {
                    __nv_bfloat16 h0 = __float2bfloat16(v0), h1 = __float2bfloat16(v1);
                    __nv_bfloat16 l0 = __float2bfloat16(v0 - __bfloat162float(h0));
                    __nv_bfloat16 l1 = __float2bfloat16(v1 - __bfloat162float(h1));
                    uint32_t hp = ((uint32_t)__bfloat16_as_ushort(h1) << 16) | __bfloat16_as_ushort(h0);
                    uint32_t lp = ((uint32_t)__bfloat16_as_ushort(l1) << 16) | __bfloat16_as_ushort(l0);
                    *(uint32_t*)(Ch + (size_t)row * N + n) = hp;
                    *(uint32_t*)(Cl + (size_t)row * N + n) = lp;
                }
            }
        }
    }
}

// ---------------- fp32 SIMT NT GEMM (relation projection + q-proj only) ----------------
template<int ACT, bool RES>
__global__ void gemm_nt(const float* __restrict__ A, const float* __restrict__ W,
                        const float* __restrict__ bias, const float* __restrict__ res,
                        float* __restrict__ C, int M, int N, int K)
{
    __shared__ float As[16][68];
    __shared__ float Ws[16][68];
    const int t  = threadIdx.x;
    const int bm = blockIdx.y * 64, bn = blockIdx.x * 64;
    const int lr = t >> 2, lk = (t & 3) * 4;
    const int ty = t >> 4, tx = t & 15;
    float acc[4][4] = {};

    for (int k0 = 0; k0 < K; k0 += 16) {
        int am = bm + lr;
        float4 av = make_float4(0.f, 0.f, 0.f, 0.f);
        if (am < M) av = *(const float4*)(A + (size_t)am * K + k0 + lk);
        As[lk + 0][lr] = av.x; As[lk + 1][lr] = av.y;
        As[lk + 2][lr] = av.z; As[lk + 3][lr] = av.w;
        int wn = bn + lr;
        float4 wv = make_float4(0.f, 0.f, 0.f, 0.f);
        if (wn < N) wv = *(const float4*)(W + (size_t)wn * K + k0 + lk);
        Ws[lk + 0][lr] = wv.x; Ws[lk + 1][lr] = wv.y;
        Ws[lk + 2][lr] = wv.z; Ws[lk + 3][lr] = wv.w;
        __syncthreads();
        #pragma unroll
        for (int kk = 0; kk < 16; kk++) {
            float4 a = *(const float4*)&As[kk][ty * 4];
            float4 b = *(const float4*)&Ws[kk][tx * 4];
            float av4[4] = {a.x, a.y, a.z, a.w};
            float bv4[4] = {b.x, b.y, b.z, b.w};
            #pragma unroll
            for (int i = 0; i < 4; i++)
                #pragma unroll
                for (int j = 0; j < 4; j++)
                    acc[i][j] += av4[i] * bv4[j];
        }
        __syncthreads();
    }
    #pragma unroll
    for (int i = 0; i < 4; i++) {
        int m = bm + ty * 4 + i;
        if (m >= M) continue;
        #pragma unroll
        for (int j = 0; j < 4; j++) {
            int n = bn + tx * 4 + j;
            if (n >= N) continue;
            float v = acc[i][j] + bias[n];
            if (RES) v += res[(size_t)m * N + n];
            if (ACT == 1) v = 0.5f * v * (1.0f + erff(v * 0.70710678118654752f));
            C[(size_t)m * N + n] = v;
        }
    }
}

// ---------------- fused weight split (one launch for all 12 weights) ----------------
struct SplitSeg { const float* src; __nv_bfloat16* h; __nv_bfloat16* l; int n; };
struct SplitArgs { SplitSeg seg[12]; int total; };

__global__ void split_all_k(SplitArgs a) {
    int i = blockIdx.x * 256 + threadIdx.x;
    if (i >= a.total) return;
    int idx = i, s = 0;
    while (idx >= a.seg[s].n) { idx -= a.seg[s].n; s++; }
    splitw(a.seg[s].src[idx], a.seg[s].h, a.seg[s].l, idx);
}

// ---------------- per-relation norms ----------------
__global__ void norms_k() {
    int r = blockIdx.x, t = threadIdx.x;
    __shared__ float red[32];
    float s = 0.f;
    for (int d = t; d < Dq; d += 256) { float x = g_proj[r * Dq + d]; s += x * x; }
    s = blockSum(s, red);
    if (t == 0) g_norm[r] = fmaxf(sqrtf(s), 1e-12f);
}

// ---------------- sims + top-k + agg(split) + states init ----------------
__global__ void sims_agg_k(const int* __restrict__ eids, const int* __restrict__ nids)
{
    int be = blockIdx.x, t = threadIdx.x;
    int lane = t & 31, w = t >> 5;
    __shared__ float se[Dq];
    __shared__ float ssim[Nq];
    __shared__ int   snid[Nq];
    __shared__ int   ssel[Kq];

    int eid = eids[be];
    for (int d = t; d < Dq; d += 256) {
        float x = g_proj[eid * Dq + d];
        se[d] = x;
        g_states[(size_t)be * Dq + d] = x;
    }
    __syncthreads();
    float en = g_norm[eid];

    for (int n = w; n < Nq; n += 8) {
        int nid = nids[be * Nq + n];
        float s = 0.f;
        for (int d = lane; d < Dq; d += 32) s += g_proj[nid * Dq + d] * se[d];
        s = warpSum(s);
        if (lane == 0) { snid[n] = nid; ssim[n] = s / (g_norm[nid] * en); }
    }
    __syncthreads();

    if (w == 0) {
        float sv = ssim[lane];
        for (int it = 0; it < Kq; it++) {
            float bs = sv; int bi = lane;
            #pragma unroll
            for (int o = 16; o; o >>= 1) {
                float os = __shfl_xor_sync(0xffffffffu, bs, o);
                int   oi = __shfl_xor_sync(0xffffffffu, bi, o);
                if (os > bs || (os == bs && oi < bi)) { bs = os; bi = oi; }
            }
            if (lane == bi) sv = -FLT_MAX;
            if (lane == 0) ssel[it] = snid[bi];
        }
    }
    __syncthreads();

    for (int d = t; d < Dq; d += 256) {
        float a = 0.f;
        #pragma unroll
        for (int k2 = 0; k2 < Kq; k2++) a += g_proj[ssel[k2] * Dq + d];
        splitw(a * (1.0f / Kq), g_agg_h, g_agg_l, (size_t)be * Dq + d);
    }
}

// ---------------- layernorm -> fp32 states + hi/lo split ----------------
template<bool MASK>
__global__ void ln_k(const float* __restrict__ in, const float* __restrict__ g,
                     const float* __restrict__ b, const float* __restrict__ mask,
                     float* __restrict__ out, __nv_bfloat16* __restrict__ oh,
                     __nv_bfloat16* __restrict__ ol)
{
    int be = blockIdx.x, t = threadIdx.x;
    __shared__ float red[32];
    const float* x = in + (size_t)be * Dq;
    float v0 = x[t], v1 = x[t + 256];
    float mu = blockSum(v0 + v1, red) * (1.0f / Dq);
    float d0 = v0 - mu, d1 = v1 - mu;
    float var = blockSum(d0 * d0 + d1 * d1, red) * (1.0f / Dq);
    float r = rsqrtf(var + EPSq);
    float mk = MASK ? mask[be] : 1.0f;
    float o0 = (d0 * r * g[t      ] + b[t      ]) * mk;
    float o1 = (d1 * r * g[t + 256] + b[t + 256]) * mk;
    size_t i0 = (size_t)be * Dq + t, i1 = i0 + 256;
    out[i0] = o0; out[i1] = o1;
    splitw(o0, oh, ol, i0);
    splitw(o1, oh, ol, i1);
}

// ---------------- no-edge flags ----------------
__global__ void noedge_k(const float* __restrict__ mask) {
    int b = blockIdx.x;
    __shared__ float red[32];
    float s = blockSum(mask[b * Eq + threadIdx.x], red);
    if (threadIdx.x == 0) g_noedge[b] = (s == 0.f) ? 0.f : 1.f;
}

// ---------------- memory-token cross attention (out: mem hi/lo) ----------------
__global__ void attn_k(const float* __restrict__ mask)
{
    int bm = blockIdx.x;
    int b = bm / Mq, m = bm % Mq;
    int t = threadIdx.x;
    __shared__ float qh[DHq];
    __shared__ float sc[Eq];
    __shared__ float red[32];
    __shared__ float outp[4][DHq];

    for (int h = 0; h < Hq; h++) {
        if (t < DHq) qh[t] = g_q[m * Dq + h * DHq + t];
        __syncthreads();

        const float* kr = g_k + ((size_t)(b * Eq + t)) * Dq + h * DHq;
        float dot = 0.f;
        #pragma unroll
        for (int d = 0; d < DHq; d++) dot += qh[d] * kr[d];
        float s = dot * 0.125f;
        if (mask[b * Eq + t] == 0.f) s = -FLT_MAX;

        float mx = blockMax(s, red);
        float e = expf(s - mx);
        sc[t] = e;
        float sum = blockSum(e, red);

        int d = t & 63, gpart = t >> 6;
        const float* vb0 = g_v + ((size_t)(b * Eq)) * Dq + h * DHq + d;
        float acc = 0.f;
        #pragma unroll 4
        for (int e2 = gpart * 64; e2 < gpart * 64 + 64; e2++)
            acc += sc[e2] * vb0[(size_t)e2 * Dq];
        outp[gpart][d] = acc;
        __syncthreads();
        if (t < DHq) {
            float o = (outp[0][t] + outp[1][t] + outp[2][t] + outp[3][t]) / sum;
            splitw(o, g_mem_h, g_mem_l, (size_t)bm * Dq + h * DHq + t);
        }
        __syncthreads();
    }
}

// ---------------- no-edge mask + split for final proj ----------------
__global__ void memmask_k() {
    int i = blockIdx.x * 256 + threadIdx.x;       // Bq*Mq*Dq = 131072
    int b = i / (Mq * Dq);
    splitw(g_mem2[i] * g_noedge[b], g_m2_h, g_m2_l, i);
}

// ---------------- launch ----------------
extern "C" void kernel_launch(void* const* d_in, const int* in_sizes, int n_in,
                              void* d_out, int out_size)
{
    const int*   edge_ids  = (const int*)  d_in[0];
    const int*   neigh_ids = (const int*)  d_in[1];
    const float* edge_mask = (const float*)d_in[2];
    const float* rel_emb   = (const float*)d_in[3];
    const float* rp_w      = (const float*)d_in[4];
    const float* rp_b      = (const float*)d_in[5];
    const float* ly_vw     = (const float*)d_in[6];
    const float* ly_vb     = (const float*)d_in[7];
    const float* ly_ow     = (const float*)d_in[8];
    const float* ly_ob     = (const float*)d_in[9];
    const float* ly_n1g    = (const float*)d_in[10];
    const float* ly_n1b    = (const float*)d_in[11];
    const float* ly_n2g    = (const float*)d_in[12];
    const float* ly_n2b    = (const float*)d_in[13];
    const float* ly_w1     = (const float*)d_in[14];
    const float* ly_b1     = (const float*)d_in[15];
    const float* ly_w2     = (const float*)d_in[16];
    const float* ly_b2     = (const float*)d_in[17];
    const float* mem_q     = (const float*)d_in[18];
    const float* t_qw      = (const float*)d_in[19];
    const float* t_qb      = (const float*)d_in[20];
    const float* t_kw      = (const float*)d_in[21];
    const float* t_kb      = (const float*)d_in[22];
    const float* t_vw      = (const float*)d_in[23];
    const float* t_vb      = (const float*)d_in[24];
    const float* t_ow      = (const float*)d_in[25];
    const float* t_ob      = (const float*)d_in[26];
    const float* proj_w    = (const float*)d_in[27];
    const float* proj_b    = (const float*)d_in[28];
    float* out = (float*)d_out;

    float *p_proj, *p_states, *p_t2, *p_k, *p_v, *p_q, *p_mem2;
    cudaGetSymbolAddress((void**)&p_proj,   g_proj);
    cudaGetSymbolAddress((void**)&p_states, g_states);
    cudaGetSymbolAddress((void**)&p_t2,     g_t2);
    cudaGetSymbolAddress((void**)&p_k,      g_k);
    cudaGetSymbolAddress((void**)&p_v,      g_v);
    cudaGetSymbolAddress((void**)&p_q,      g_q);
    cudaGetSymbolAddress((void**)&p_mem2,   g_mem2);

    __nv_bfloat16 *p_agg_h, *p_agg_l, *p_t1_h, *p_t1_l, *p_st_h, *p_st_l;
    __nv_bfloat16 *p_hid_h, *p_hid_l, *p_mem_h, *p_mem_l, *p_m2_h, *p_m2_l;
    cudaGetSymbolAddress((void**)&p_agg_h,  g_agg_h);
    cudaGetSymbolAddress((void**)&p_agg_l,  g_agg_l);
    cudaGetSymbolAddress((void**)&p_t1_h,   g_t1_h);
    cudaGetSymbolAddress((void**)&p_t1_l,   g_t1_l);
    cudaGetSymbolAddress((void**)&p_st_h,   g_st_h);
    cudaGetSymbolAddress((void**)&p_st_l,   g_st_l);
    cudaGetSymbolAddress((void**)&p_hid_h,  g_hid_h);
    cudaGetSymbolAddress((void**)&p_hid_l,  g_hid_l);
    cudaGetSymbolAddress((void**)&p_mem_h,  g_mem_h);
    cudaGetSymbolAddress((void**)&p_mem_l,  g_mem_l);
    cudaGetSymbolAddress((void**)&p_m2_h,   g_m2_h);
    cudaGetSymbolAddress((void**)&p_m2_l,   g_m2_l);

    __nv_bfloat16 *p_wv_h, *p_wv_l, *p_wo_h, *p_wo_l, *p_w1_h, *p_w1_l, *p_w2_h, *p_w2_l;
    __nv_bfloat16 *p_tk_h, *p_tk_l, *p_tv_h, *p_tv_l, *p_to_h, *p_to_l, *p_pw_h, *p_pw_l;
    cudaGetSymbolAddress((void**)&p_wv_h, g_wv_h);
    cudaGetSymbolAddress((void**)&p_wv_l, g_wv_l);
    cudaGetSymbolAddress((void**)&p_wo_h, g_wo_h);
    cudaGetSymbolAddress((void**)&p_wo_l, g_wo_l);
    cudaGetSymbolAddress((void**)&p_w1_h, g_w1_h);
    cudaGetSymbolAddress((void**)&p_w1_l, g_w1_l);
    cudaGetSymbolAddress((void**)&p_w2_h, g_w2_h);
    cudaGetSymbolAddress((void**)&p_w2_l, g_w2_l);
    cudaGetSymbolAddress((void**)&p_tk_h, g_tk_h);
    cudaGetSymbolAddress((void**)&p_tk_l, g_tk_l);
    cudaGetSymbolAddress((void**)&p_tv_h, g_tv_h);
    cudaGetSymbolAddress((void**)&p_tv_l, g_tv_l);
    cudaGetSymbolAddress((void**)&p_to_h, g_to_h);
    cudaGetSymbolAddress((void**)&p_to_l, g_to_l);
    cudaGetSymbolAddress((void**)&p_pw_h, g_pw_h);
    cudaGetSymbolAddress((void**)&p_pw_l, g_pw_l);

    constexpr int DD = Dq * Dq, DD4 = 4 * Dq * Dq;

    // mma instantiations + dynamic smem sizes
    auto kA = mma_nt<128,64,4,2, 0,false,false,true>;   // split out
    auto kB = mma_nt<128,64,4,2, 0,true ,true ,false>;  // res + f32 out
    auto kC = mma_nt<128,128,2,4, 1,false,false,true>;  // gelu + split out
    auto kD = mma_nt<128,64,4,2, 0,false,true ,false>;  // f32 out
    constexpr int SM64  = (128 + 64)  * PADK * 2 * NSTG;  // 61440
    constexpr int SM128 = (128 + 128) * PADK * 2 * NSTG;  // 81920
    cudaFuncSetAttribute(kA, cudaFuncAttributeMaxDynamicSharedMemorySize, SM64);
    cudaFuncSetAttribute(kB, cudaFuncAttributeMaxDynamicSharedMemorySize, SM64);
    cudaFuncSetAttribute(kC, cudaFuncAttributeMaxDynamicSharedMemorySize, SM128);
    cudaFuncSetAttribute(kD, cudaFuncAttributeMaxDynamicSharedMemorySize, SM64);

    // 0) fused weight splits (12 segments, one launch)
    {
        SplitArgs sa;
        int s = 0, tot = 0;
        auto add = [&](const float* src, __nv_bfloat16* h, __nv_bfloat16* l, int n) {
            sa.seg[s++] = SplitSeg{src, h, l, n}; tot += n;
        };
        for (int l = 0; l < Lq; l++) {
            add(ly_vw + (size_t)l * DD,  p_wv_h + (size_t)l * DD,  p_wv_l + (size_t)l * DD,  DD);
            add(ly_ow + (size_t)l * DD,  p_wo_h + (size_t)l * DD,  p_wo_l + (size_t)l * DD,  DD);
            add(ly_w1 + (size_t)l * DD4, p_w1_h + (size_t)l * DD4, p_w1_l + (size_t)l * DD4, DD4);
            add(ly_w2 + (size_t)l * DD4, p_w2_h + (size_t)l * DD4, p_w2_l + (size_t)l * DD4, DD4);
        }
        add(t_kw,   p_tk_h, p_tk_l, DD);
        add(t_vw,   p_tv_h, p_tv_l, DD);
        add(t_ow,   p_to_h, p_to_l, DD);
        add(proj_w, p_pw_h, p_pw_l, HLLMq * Dq);
        sa.total = tot;
        split_all_k<<<(tot + 255) / 256, 256>>>(sa);
    }

    // 1) relation projection (fp32 SIMT — feeds discrete top-k, must stay fp32)
    gemm_nt<0,false><<<dim3(Dq/64, (Rq + 63)/64), 256>>>(rel_emb, rp_w, rp_b, nullptr,
                                                         p_proj, Rq, Dq, RDq);
    norms_k<<<Rq, 256>>>();
    sims_agg_k<<<BEq, 256>>>(edge_ids, neigh_ids);

    // 2) relation-context layers
    for (int l = 0; l < Lq; l++) {
        kA<<<dim3(Dq/64, BEq/128), 256, SM64>>>(
            p_agg_h, p_agg_l, p_wv_h + (size_t)l*DD, p_wv_l + (size_t)l*DD,
            ly_vb + l*Dq, nullptr, nullptr, p_t1_h, p_t1_l, BEq, Dq, Dq);

        kB<<<dim3(Dq/64, BEq/128), 256, SM64>>>(
            p_t1_h, p_t1_l, p_wo_h + (size_t)l*DD, p_wo_l + (size_t)l*DD,
            ly_ob + l*Dq, p_states, p_t2, nullptr, nullptr, BEq, Dq, Dq);
        ln_k<false><<<BEq, 256>>>(p_t2, ly_n1g + l*Dq, ly_n1b + l*Dq, nullptr,
                                  p_states, p_st_h, p_st_l);

        kC<<<dim3(4*Dq/128, BEq/128), 256, SM128>>>(
            p_st_h, p_st_l, p_w1_h + (size_t)l*DD4, p_w1_l + (size_t)l*DD4,
            ly_b1 + l*4*Dq, nullptr, nullptr, p_hid_h, p_hid_l, BEq, 4*Dq, Dq);

        kB<<<dim3(Dq/64, BEq/128), 256, SM64>>>(
            p_hid_h, p_hid_l, p_w2_h + (size_t)l*DD4, p_w2_l + (size_t)l*DD4,
            ly_b2 + l*Dq, p_states, p_t2, nullptr, nullptr, BEq, Dq, 4*Dq);
        ln_k<true><<<BEq, 256>>>(p_t2, ly_n2g + l*Dq, ly_n2b + l*Dq, edge_mask,
                                 p_states, p_st_h, p_st_l);
    }

    // 3) tokenizer projections
    gemm_nt<0,false><<<dim3(Dq/64, 1), 256>>>(mem_q, t_qw, t_qb, nullptr, p_q, Mq, Dq, Dq);
    kD<<<dim3(Dq/64, BEq/128), 256, SM64>>>(
        p_st_h, p_st_l, p_tk_h, p_tk_l, t_kb, nullptr, p_k, nullptr, nullptr, BEq, Dq, Dq);
    kD<<<dim3(Dq/64, BEq/128), 256, SM64>>>(
        p_st_h, p_st_l, p_tv_h, p_tv_l, t_vb, nullptr, p_v, nullptr, nullptr, BEq, Dq, Dq);

    // 4) attention + output proj + no-edge masking
    noedge_k<<<Bq, 256>>>(edge_mask);
    attn_k<<<Bq * Mq, 256>>>(edge_mask);
    kD<<<dim3(Dq/64, (Bq*Mq)/128), 256, SM64>>>(
        p_mem_h, p_mem_l, p_to_h, p_to_l, t_ob, nullptr, p_mem2, nullptr, nullptr, Bq*Mq, Dq, Dq);
    memmask_k<<<(Bq*Mq*Dq)/256, 256>>>();

    // 5) LLM projection -> d_out
    kD<<<dim3(HLLMq/64, (Bq*Mq)/128), 256, SM64>>>(
        p_m2_h, p_m2_l, p_pw_h, p_pw_l, proj_b, nullptr, out, nullptr, nullptr, Bq*Mq, HLLMq, Dq);
}

// round 5
// speedup vs baseline: 1.4630x; 1.0362x over previous
#include <cuda_runtime.h>
#include <cuda_bf16.h>
#include <math.h>
#include <float.h>
#include <stdint.h>

// ---------------- problem constants ----------------
constexpr int Bq = 8, Eq = 256, Nq = 32;
constexpr int Dq = 512, RDq = 768, Rq = 2000;
constexpr int Lq = 2, Kq = 8, Mq = 32, Hq = 8, DHq = 64;
constexpr int HLLMq = 4096;
constexpr int BEq = Bq * Eq;          // 2048 edge tokens
constexpr float EPSq = 1e-5f;

// ---------------- scratch (device globals; no allocs allowed) ----------------
__device__ float g_proj  [Rq * Dq];
__device__ float g_states[BEq * Dq];
__device__ float g_t2    [BEq * Dq];
__device__ float g_kv    [BEq * 2 * Dq];   // [2048, 1024]: k | v
__device__ float g_kvb   [2 * Dq];
__device__ float g_q     [Mq * Dq];
__device__ float g_mem2  [Bq * Mq * Dq];
__device__ float g_noedge[Bq];
__device__ float g_vwT   [Dq * Dq];        // transpose scratch (reused per layer)
__device__ float g_cb    [Lq][Dq];         // folded attn bias
__device__ float g_zero512[Dq];            // never written: zero bias
// bf16 hi/lo split activation buffers
__device__ __align__(256) __nv_bfloat16 g_agg_h[BEq * Dq],      g_agg_l[BEq * Dq];
__device__ __align__(256) __nv_bfloat16 g_st_h [BEq * Dq],      g_st_l [BEq * Dq];
__device__ __align__(256) __nv_bfloat16 g_hid_h[BEq * 4 * Dq],  g_hid_l[BEq * 4 * Dq];
__device__ __align__(256) __nv_bfloat16 g_mem_h[Bq * Mq * Dq],  g_mem_l[Bq * Mq * Dq];
__device__ __align__(256) __nv_bfloat16 g_m2_h [Bq * Mq * Dq],  g_m2_l [Bq * Mq * Dq];
// bf16 hi/lo split weight buffers
__device__ __align__(256) __nv_bfloat16 g_wc_h[Lq][Dq * Dq],     g_wc_l[Lq][Dq * Dq];
__device__ __align__(256) __nv_bfloat16 g_w1_h[Lq][4 * Dq * Dq], g_w1_l[Lq][4 * Dq * Dq];
__device__ __align__(256) __nv_bfloat16 g_w2_h[Lq][4 * Dq * Dq], g_w2_l[Lq][4 * Dq * Dq];
__device__ __align__(256) __nv_bfloat16 g_kvw_h[2 * Dq * Dq],    g_kvw_l[2 * Dq * Dq];
__device__ __align__(256) __nv_bfloat16 g_to_h[Dq * Dq],         g_to_l[Dq * Dq];
__device__ __align__(256) __nv_bfloat16 g_pw_h[HLLMq * Dq],      g_pw_l[HLLMq * Dq];

__device__ __forceinline__ void splitw(float v, __nv_bfloat16* H, __nv_bfloat16* L, size_t i) {
    __nv_bfloat16 h = __float2bfloat16(v);
    H[i] = h;
    L[i] = __float2bfloat16(v - __bfloat162float(h));
}

__device__ __forceinline__ uint32_t smem_u32(const void* p) {
    uint32_t a;
    asm("{ .reg .u64 t; cvta.to.shared.u64 t, %1; cvt.u32.u64 %0, t; }" : "=r"(a) : "l"(p));
    return a;
}

// ---------------- reductions ----------------
__device__ __forceinline__ float warpSum(float v) {
    #pragma unroll
    for (int o = 16; o; o >>= 1) v += __shfl_xor_sync(0xffffffffu, v, o);
    return v;
}
__device__ __forceinline__ float warpMax(float v) {
    #pragma unroll
    for (int o = 16; o; o >>= 1) v = fmaxf(v, __shfl_xor_sync(0xffffffffu, v, o));
    return v;
}
__device__ __forceinline__ float blockSum(float v, float* red) {
    int lane = threadIdx.x & 31, w = threadIdx.x >> 5;
    int nw = blockDim.x >> 5;
    v = warpSum(v);
    if (lane == 0) red[w] = v;
    __syncthreads();
    if (w == 0) {
        float r = (lane < nw) ? red[lane] : 0.f;
        r = warpSum(r);
        if (lane == 0) red[0] = r;
    }
    __syncthreads();
    float out = red[0];
    __syncthreads();
    return out;
}
__device__ __forceinline__ float blockMax(float v, float* red) {
    int lane = threadIdx.x & 31, w = threadIdx.x >> 5;
    int nw = blockDim.x >> 5;
    v = warpMax(v);
    if (lane == 0) red[w] = v;
    __syncthreads();
    if (w == 0) {
        float r = (lane < nw) ? red[lane] : -FLT_MAX;
        r = warpMax(r);
        if (lane == 0) red[0] = r;
    }
    __syncthreads();
    float out = red[0];
    __syncthreads();
    return out;
}

// ---------------- mma.sync primitives ----------------
__device__ __forceinline__ void mma16816(float* d, const uint32_t* a, const uint32_t* b) {
    asm volatile("mma.sync.aligned.m16n8k16.row.col.f32.bf16.bf16.f32 "
        "{%0,%1,%2,%3}, {%4,%5,%6,%7}, {%8,%9}, {%0,%1,%2,%3};"
        : "+f"(d[0]), "+f"(d[1]), "+f"(d[2]), "+f"(d[3])
        : "r"(a[0]), "r"(a[1]), "r"(a[2]), "r"(a[3]), "r"(b[0]), "r"(b[1]));
}
__device__ __forceinline__ void ldsm4(uint32_t& r0, uint32_t& r1, uint32_t& r2, uint32_t& r3,
                                      uint32_t addr) {
    asm volatile("ldmatrix.sync.aligned.m8n8.x4.shared.b16 {%0,%1,%2,%3}, [%4];"
        : "=r"(r0), "=r"(r1), "=r"(r2), "=r"(r3) : "r"(addr));
}
__device__ __forceinline__ void cpasync16(uint32_t dst, const void* src) {
    asm volatile("cp.async.cg.shared.global [%0], [%1], 16;\n" :: "r"(dst), "l"(src) : "memory");
}

// ================= bf16x3 NT GEMM via mma.sync, 4-stage pipeline =================
constexpr int PADK = 40;
constexpr int NSTG = 4;

template<int TM, int TN, int WR, int WC, int ACT, bool RES, bool WF32, bool WSPLIT>
__global__ __launch_bounds__(256)
void mma_nt(const __nv_bfloat16* __restrict__ Ah, const __nv_bfloat16* __restrict__ Al,
            const __nv_bfloat16* __restrict__ Bh, const __nv_bfloat16* __restrict__ Bl,
            const float* __restrict__ bias, const float* __restrict__ res,
            float* __restrict__ Cf, __nv_bfloat16* __restrict__ Ch, __nv_bfloat16* __restrict__ Cl,
            int M, int N, int K)
{
    extern __shared__ __align__(128) __nv_bfloat16 smem[];
    constexpr int STG_E = (TM + TN) * PADK;
    constexpr int tm = TM / WR, tn = TN / WC;
    constexpr int MT = tm / 16, NT = tn / 8;

    const int tid = threadIdx.x;
    const int wid = tid >> 5, lane = tid & 31;
    const int bm = blockIdx.y * TM, bn = blockIdx.x * TN;
    const int wm = (wid / WC) * tm, wn = (wid % WC) * tn;
    const uint32_t sbase = smem_u32(smem);

    const int NI = (3 * K) / 32;

    auto load_stage = [&](int stage, int buf) {
        int c0 = stage * 32;
        int term = c0 / K;
        int kk = c0 - term * K;
        const __nv_bfloat16* As = (term < 2) ? Ah : Al;
        const __nv_bfloat16* Bs = (term == 1) ? Bl : Bh;
        uint32_t base = sbase + (uint32_t)buf * STG_E * 2;
        constexpr int CHA = TM * 4, CH = (TM + TN) * 4;
        #pragma unroll
        for (int j = 0; j < CH / 256; ++j) {
            int f = tid + 256 * j;
            if (f < CHA) {
                int row = f >> 2, ch = f & 3;
                cpasync16(base + (uint32_t)(row * PADK + ch * 8) * 2,
                          As + (size_t)(bm + row) * K + kk + ch * 8);
            } else {
                int f2 = f - CHA;
                int row = f2 >> 2, ch = f2 & 3;
                cpasync16(base + (uint32_t)(TM * PADK + row * PADK + ch * 8) * 2,
                          Bs + (size_t)(bn + row) * K + kk + ch * 8);
            }
        }
        asm volatile("cp.async.commit_group;\n" ::: "memory");
    };

    float d[MT][NT][4];
    #pragma unroll
    for (int a = 0; a < MT; a++)
        #pragma unroll
        for (int b = 0; b < NT; b++)
            #pragma unroll
            for (int c = 0; c < 4; c++) d[a][b][c] = 0.f;

    load_stage(0, 0);
    load_stage(1, 1);
    load_stage(2, 2);

    const int a_lrow = lane & 15, a_lk = (lane >> 4) * 8;
    const int bq = lane >> 3;
    const int b_lrow = (lane & 7) + ((bq >> 1) * 8);
    const int b_lk = (bq & 1) * 8;

    for (int i = 0; i < NI; ++i) {
        if (i + 3 <= NI)      asm volatile("cp.async.wait_group 2;\n" ::: "memory");
        else if (i + 2 == NI) asm volatile("cp.async.wait_group 1;\n" ::: "memory");
        else                  asm volatile("cp.async.wait_group 0;\n" ::: "memory");
        __syncthreads();

        if (i + 3 < NI) load_stage(i + 3, (i + 3) & (NSTG - 1));

        const uint32_t abase = sbase + (uint32_t)(i & (NSTG - 1)) * STG_E * 2;
        const uint32_t bbase = abase + TM * PADK * 2;

        #pragma unroll
        for (int kh = 0; kh < 2; ++kh) {
            const int kc = kh * 16;
            uint32_t afr[MT][4];
            #pragma unroll
            for (int mt = 0; mt < MT; ++mt)
                ldsm4(afr[mt][0], afr[mt][1], afr[mt][2], afr[mt][3],
                      abase + (uint32_t)((wm + mt * 16 + a_lrow) * PADK + kc + a_lk) * 2);
            uint32_t bfr[NT][2];
            #pragma unroll
            for (int nt2 = 0; nt2 < NT / 2; ++nt2) {
                uint32_t r0, r1, r2, r3;
                ldsm4(r0, r1, r2, r3,
                      bbase + (uint32_t)((wn + nt2 * 16 + b_lrow) * PADK + kc + b_lk) * 2);
                bfr[nt2 * 2][0] = r0; bfr[nt2 * 2][1] = r1;
                bfr[nt2 * 2 + 1][0] = r2; bfr[nt2 * 2 + 1][1] = r3;
            }
            #pragma unroll
            for (int mt = 0; mt < MT; ++mt)
                #pragma unroll
                for (int nt = 0; nt < NT; ++nt)
                    mma16816(d[mt][nt], afr[mt], bfr[nt]);
        }
    }

    const int erow = lane >> 2, ecol = (lane & 3) * 2;
    #pragma unroll
    for (int mt = 0; mt < MT; ++mt) {
        #pragma unroll
        for (int h = 0; h < 2; ++h) {
            const int row = bm + wm + mt * 16 + erow + h * 8;
            #pragma unroll
            for (int nt = 0; nt < NT; ++nt) {
                const int n = bn + wn + nt * 8 + ecol;
                float v0 = d[mt][nt][h * 2 + 0];
                float v1 = d[mt][nt][h * 2 + 1];
                float2 bv = *(const float2*)(bias + n);
                v0 += bv.x; v1 += bv.y;
                if (RES) {
                    float2 rv = *(const float2*)(res + (size_t)row * N + n);
                    v0 += rv.x; v1 += rv.y;
                }
                if (ACT == 1) {
                    v0 = 0.5f * v0 * (1.0f + erff(v0 * 0.70710678118654752f));
                    v1 = 0.5f * v1 * (1.0f + erff(v1 * 0.70710678118654752f));
                }
                if (WF32)
                    *(float2*)(Cf + (size_t)row * N + n) = make_float2(v0, v1);
                if (WSPLIT) {
                    __nv_bfloat16 h0 = __float2bfloat16(v0), h1 = __float2bfloat16(v1);
                    __nv_bfloat16 l0 = __float2bfloat16(v0 - __bfloat162float(h0));
                    __nv_bfloat16 l1 = __float2bfloat16(v1 - __bfloat162float(h1));
                    uint32_t hp = ((uint32_t)__bfloat16_as_ushort(h1) << 16) | __bfloat16_as_ushort(h0);
                    uint32_t lp = ((uint32_t)__bfloat16_as_ushort(l1) << 16) | __bfloat16_as_ushort(l0);
                    *(uint32_t*)(Ch + (size_t)row * N + n) = hp;
                    *(uint32_t*)(Cl + (size_t)row * N + n) = lp;
                }
            }
        }
    }
}

// ---------------- fp32 SIMT NT GEMM ----------------
// WSPLIT: write bf16 hi/lo instead of / in addition to f32.
template<int ACT, bool WF32, bool WSPLIT>
__global__ void gemm_nt(const float* __restrict__ A, const float* __restrict__ W,
                        const float* __restrict__ bias,
                        float* __restrict__ C, __nv_bfloat16* __restrict__ Ch,
                        __nv_bfloat16* __restrict__ Cl, int M, int N, int K)
{
    __shared__ float As[16][68];
    __shared__ float Ws[16][68];
    const int t  = threadIdx.x;
    const int bm = blockIdx.y * 64, bn = blockIdx.x * 64;
    const int lr = t >> 2, lk = (t & 3) * 4;
    const int ty = t >> 4, tx = t & 15;
    float acc[4][4] = {};

    for (int k0 = 0; k0 < K; k0 += 16) {
        int am = bm + lr;
        float4 av = make_float4(0.f, 0.f, 0.f, 0.f);
        if (am < M) av = *(const float4*)(A + (size_t)am * K + k0 + lk);
        As[lk + 0][lr] = av.x; As[lk + 1][lr] = av.y;
        As[lk + 2][lr] = av.z; As[lk + 3][lr] = av.w;
        int wn = bn + lr;
        float4 wv = make_float4(0.f, 0.f, 0.f, 0.f);
        if (wn < N) wv = *(const float4*)(W + (size_t)wn * K + k0 + lk);
        Ws[lk + 0][lr] = wv.x; Ws[lk + 1][lr] = wv.y;
        Ws[lk + 2][lr] = wv.z; Ws[lk + 3][lr] = wv.w;
        __syncthreads();
        #pragma unroll
        for (int kk = 0; kk < 16; kk++) {
            float4 a = *(const float4*)&As[kk][ty * 4];
            float4 b = *(const float4*)&Ws[kk][tx * 4];
            float av4[4] = {a.x, a.y, a.z, a.w};
            float bv4[4] = {b.x, b.y, b.z, b.w};
            #pragma unroll
            for (int i = 0; i < 4; i++)
                #pragma unroll
                for (int j = 0; j < 4; j++)
                    acc[i][j] += av4[i] * bv4[j];
        }
        __syncthreads();
    }
    #pragma unroll
    for (int i = 0; i < 4; i++) {
        int m = bm + ty * 4 + i;
        if (m >= M) continue;
        #pragma unroll
        for (int j = 0; j < 4; j++) {
            int n = bn + tx * 4 + j;
            if (n >= N) continue;
            float v = acc[i][j] + bias[n];
            if (ACT == 1) v = 0.5f * v * (1.0f + erff(v * 0.70710678118654752f));
            if (WF32) C[(size_t)m * N + n] = v;
            if (WSPLIT) splitw(v, Ch, Cl, (size_t)m * N + n);
        }
    }
}

// ---------------- fold prep: transpose vw + folded bias cb = ow@vb + ob ----------------
__global__ void fold_prep_k(const float* __restrict__ vw, const float* __restrict__ ow,
                            const float* __restrict__ vb, const float* __restrict__ ob,
                            float* __restrict__ vwT, float* __restrict__ cb)
{
    __shared__ float tile[32][33];
    const int bx = blockIdx.x, by = blockIdx.y;    // grid (16,16)
    const int t = threadIdx.x;                     // 256
    const int tx = t & 31, ty = t >> 5;            // 32 x 8
    #pragma unroll
    for (int r = 0; r < 4; r++)
        tile[ty + r * 8][tx] = vw[(size_t)(by * 32 + ty + r * 8) * Dq + bx * 32 + tx];
    __syncthreads();
    #pragma unroll
    for (int r = 0; r < 4; r++)
        vwT[(size_t)(bx * 32 + ty + r * 8) * Dq + by * 32 + tx] = tile[tx][ty + r * 8];

    if (by == 0) {
        int n = bx * 32 + (t >> 3), ks = t & 7;
        float p = 0.f;
        for (int k = ks * 64; k < ks * 64 + 64; k++) p += ow[(size_t)n * Dq + k] * vb[k];
        p += __shfl_xor_sync(0xffffffffu, p, 1);
        p += __shfl_xor_sync(0xffffffffu, p, 2);
        p += __shfl_xor_sync(0xffffffffu, p, 4);
        if (ks == 0) cb[n] = p + ob[n];
    }
}

// ---------------- fused weight split ----------------
struct SplitSeg { const float* src; __nv_bfloat16* h; __nv_bfloat16* l; int n; };
struct SplitArgs { SplitSeg seg[12]; int total; };

__global__ void split_all_k(SplitArgs a) {
    int i = blockIdx.x * 256 + threadIdx.x;
    if (i >= a.total) return;
    int idx = i, s = 0;
    while (idx >= a.seg[s].n) { idx -= a.seg[s].n; s++; }
    splitw(a.seg[s].src[idx], a.seg[s].h, a.seg[s].l, idx);
}

// ---------------- sims + inline norms + top-k + agg(split) + states init ----------------
__global__ void sims_agg_k(const int* __restrict__ eids, const int* __restrict__ nids)
{
    int be = blockIdx.x, t = threadIdx.x;
    int lane = t & 31, w = t >> 5;
    __shared__ float se[Dq];
    __shared__ float ssim[Nq];
    __shared__ int   snid[Nq];
    __shared__ int   ssel[Kq];
    __shared__ float red[32];

    int eid = eids[be];
    float sq = 0.f;
    for (int d = t; d < Dq; d += 256) {
        float x = g_proj[eid * Dq + d];
        se[d] = x;
        g_states[(size_t)be * Dq + d] = x;
        sq += x * x;
    }
    float en = fmaxf(sqrtf(blockSum(sq, red)), 1e-12f);   // sync publishes se

    for (int n = w; n < Nq; n += 8) {
        int nid = nids[be * Nq + n];
        float s = 0.f, q = 0.f;
        for (int d = lane; d < Dq; d += 32) {
            float p = g_proj[nid * Dq + d];
            s += p * se[d];
            q += p * p;
        }
        s = warpSum(s); q = warpSum(q);
        if (lane == 0) {
            snid[n] = nid;
            ssim[n] = s / (fmaxf(sqrtf(q), 1e-12f) * en);
        }
    }
    __syncthreads();

    if (w == 0) {
        float sv = ssim[lane];
        for (int it = 0; it < Kq; it++) {
            float bs = sv; int bi = lane;
            #pragma unroll
            for (int o = 16; o; o >>= 1) {
                float os = __shfl_xor_sync(0xffffffffu, bs, o);
                int   oi = __shfl_xor_sync(0xffffffffu, bi, o);
                if (os > bs || (os == bs && oi < bi)) { bs = os; bi = oi; }
            }
            if (lane == bi) sv = -FLT_MAX;
            if (lane == 0) ssel[it] = snid[bi];
        }
    }
    __syncthreads();

    for (int d = t; d < Dq; d += 256) {
        float a = 0.f;
        #pragma unroll
        for (int k2 = 0; k2 < Kq; k2++) a += g_proj[ssel[k2] * Dq + d];
        splitw(a * (1.0f / Kq), g_agg_h, g_agg_l, (size_t)be * Dq + d);
    }
}

// ---------------- layernorm -> fp32 states + hi/lo split ----------------
template<bool MASK>
__global__ void ln_k(const float* __restrict__ in, const float* __restrict__ g,
                     const float* __restrict__ b, const float* __restrict__ mask,
                     float* __restrict__ out, __nv_bfloat16* __restrict__ oh,
                     __nv_bfloat16* __restrict__ ol)
{
    int be = blockIdx.x, t = threadIdx.x;
    __shared__ float red[32];
    const float* x = in + (size_t)be * Dq;
    float v0 = x[t], v1 = x[t + 256];
    float mu = blockSum(v0 + v1, red) * (1.0f / Dq);
    float d0 = v0 - mu, d1 = v1 - mu;
    float var = blockSum(d0 * d0 + d1 * d1, red) * (1.0f / Dq);
    float r = rsqrtf(var + EPSq);
    float mk = MASK ? mask[be] : 1.0f;
    float o0 = (d0 * r * g[t      ] + b[t      ]) * mk;
    float o1 = (d1 * r * g[t + 256] + b[t + 256]) * mk;
    size_t i0 = (size_t)be * Dq + t, i1 = i0 + 256;
    out[i0] = o0; out[i1] = o1;
    splitw(o0, oh, ol, i0);
    splitw(o1, oh, ol, i1);
}

// ---------------- pack kv bias ----------------
__global__ void pack_kvb_k(const float* __restrict__ kb, const float* __restrict__ vb) {
    int i = blockIdx.x * 256 + threadIdx.x;    // 1024
    g_kvb[i] = (i < Dq) ? kb[i] : vb[i - Dq];
}

// ---------------- no-edge flags ----------------
__global__ void noedge_k(const float* __restrict__ mask) {
    int b = blockIdx.x;
    __shared__ float red[32];
    float s = blockSum(mask[b * Eq + threadIdx.x], red);
    if (threadIdx.x == 0) g_noedge[b] = (s == 0.f) ? 0.f : 1.f;
}

// ---------------- memory-token cross attention, head-parallel ----------------
__global__ void attn_k(const float* __restrict__ mask)
{
    int bmh = blockIdx.x;                    // B*M*H = 2048
    int h = bmh & 7, bm = bmh >> 3;
    int b = bm >> 5, m = bm & 31;
    int t = threadIdx.x;
    __shared__ float qh[DHq];
    __shared__ float sc[Eq];
    __shared__ float red[32];
    __shared__ float outp[4][DHq];

    if (t < DHq) qh[t] = g_q[m * Dq + h * DHq + t];
    __syncthreads();

    const float* kr = g_kv + (size_t)(b * Eq + t) * (2 * Dq) + h * DHq;
    float dot = 0.f;
    #pragma unroll
    for (int d = 0; d < DHq; d++) dot += qh[d] * kr[d];
    float s = dot * 0.125f;
    if (mask[b * Eq + t] == 0.f) s = -FLT_MAX;

    float mx = blockMax(s, red);
    float e = expf(s - mx);
    sc[t] = e;
    float sum = blockSum(e, red);            // sync publishes sc

    int d = t & 63, gp = t >> 6;
    const float* vb0 = g_kv + (size_t)(b * Eq) * (2 * Dq) + Dq + h * DHq + d;
    float acc = 0.f;
    #pragma unroll 4
    for (int e2 = gp * 64; e2 < gp * 64 + 64; e2++)
        acc += sc[e2] * vb0[(size_t)e2 * (2 * Dq)];
    outp[gp][d] = acc;
    __syncthreads();
    if (t < DHq) {
        float o = (outp[0][t] + outp[1][t] + outp[2][t] + outp[3][t]) / sum;
        splitw(o, g_mem_h, g_mem_l, (size_t)bm * Dq + h * DHq + t);
    }
}

// ---------------- no-edge mask + split for final proj ----------------
__global__ void memmask_k() {
    int i = blockIdx.x * 256 + threadIdx.x;
    int b = i / (Mq * Dq);
    splitw(g_mem2[i] * g_noedge[b], g_m2_h, g_m2_l, i);
}

// ---------------- launch ----------------
extern "C" void kernel_launch(void* const* d_in, const int* in_sizes, int n_in,
                              void* d_out, int out_size)
{
    const int*   edge_ids  = (const int*)  d_in[0];
    const int*   neigh_ids = (const int*)  d_in[1];
    const float* edge_mask = (const float*)d_in[2];
    const float* rel_emb   = (const float*)d_in[3];
    const float* rp_w      = (const float*)d_in[4];
    const float* rp_b      = (const float*)d_in[5];
    const float* ly_vw     = (const float*)d_in[6];
    const float* ly_vb     = (const float*)d_in[7];
    const float* ly_ow     = (const float*)d_in[8];
    const float* ly_ob     = (const float*)d_in[9];
    const float* ly_n1g    = (const float*)d_in[10];
    const float* ly_n1b    = (const float*)d_in[11];
    const float* ly_n2g    = (const float*)d_in[12];
    const float* ly_n2b    = (const float*)d_in[13];
    const float* ly_w1     = (const float*)d_in[14];
    const float* ly_b1     = (const float*)d_in[15];
    const float* ly_w2     = (const float*)d_in[16];
    const float* ly_b2     = (const float*)d_in[17];
    const float* mem_q     = (const float*)d_in[18];
    const float* t_qw      = (const float*)d_in[19];
    const float* t_qb      = (const float*)d_in[20];
    const float* t_kw      = (const float*)d_in[21];
    const float* t_kb      = (const float*)d_in[22];
    const float* t_vw      = (const float*)d_in[23];
    const float* t_vb      = (const float*)d_in[24];
    const float* t_ow      = (const float*)d_in[25];
    const float* t_ob      = (const float*)d_in[26];
    const float* proj_w    = (const float*)d_in[27];
    const float* proj_b    = (const float*)d_in[28];
    float* out = (float*)d_out;

    float *p_proj, *p_states, *p_t2, *p_kv, *p_kvb, *p_q, *p_mem2, *p_vwT, *p_cb, *p_zero;
    cudaGetSymbolAddress((void**)&p_proj,   g_proj);
    cudaGetSymbolAddress((void**)&p_states, g_states);
    cudaGetSymbolAddress((void**)&p_t2,     g_t2);
    cudaGetSymbolAddress((void**)&p_kv,     g_kv);
    cudaGetSymbolAddress((void**)&p_kvb,    g_kvb);
    cudaGetSymbolAddress((void**)&p_q,      g_q);
    cudaGetSymbolAddress((void**)&p_mem2,   g_mem2);
    cudaGetSymbolAddress((void**)&p_vwT,    g_vwT);
    cudaGetSymbolAddress((void**)&p_cb,     g_cb);
    cudaGetSymbolAddress((void**)&p_zero,   g_zero512);

    __nv_bfloat16 *p_agg_h, *p_agg_l, *p_st_h, *p_st_l, *p_hid_h, *p_hid_l;
    __nv_bfloat16 *p_mem_h, *p_mem_l, *p_m2_h, *p_m2_l;
    cudaGetSymbolAddress((void**)&p_agg_h,  g_agg_h);
    cudaGetSymbolAddress((void**)&p_agg_l,  g_agg_l);
    cudaGetSymbolAddress((void**)&p_st_h,   g_st_h);
    cudaGetSymbolAddress((void**)&p_st_l,   g_st_l);
    cudaGetSymbolAddress((void**)&p_hid_h,  g_hid_h);
    cudaGetSymbolAddress((void**)&p_hid_l,  g_hid_l);
    cudaGetSymbolAddress((void**)&p_mem_h,  g_mem_h);
    cudaGetSymbolAddress((void**)&p_mem_l,  g_mem_l);
    cudaGetSymbolAddress((void**)&p_m2_h,   g_m2_h);
    cudaGetSymbolAddress((void**)&p_m2_l,   g_m2_l);

    __nv_bfloat16 *p_wc_h, *p_wc_l, *p_w1_h, *p_w1_l, *p_w2_h, *p_w2_l;
    __nv_bfloat16 *p_kvw_h, *p_kvw_l, *p_to_h, *p_to_l, *p_pw_h, *p_pw_l;
    cudaGetSymbolAddress((void**)&p_wc_h, g_wc_h);
    cudaGetSymbolAddress((void**)&p_wc_l, g_wc_l);
    cudaGetSymbolAddress((void**)&p_w1_h, g_w1_h);
    cudaGetSymbolAddress((void**)&p_w1_l, g_w1_l);
    cudaGetSymbolAddress((void**)&p_w2_h, g_w2_h);
    cudaGetSymbolAddress((void**)&p_w2_l, g_w2_l);
    cudaGetSymbolAddress((void**)&p_kvw_h, g_kvw_h);
    cudaGetSymbolAddress((void**)&p_kvw_l, g_kvw_l);
    cudaGetSymbolAddress((void**)&p_to_h, g_to_h);
    cudaGetSymbolAddress((void**)&p_to_l, g_to_l);
    cudaGetSymbolAddress((void**)&p_pw_h, g_pw_h);
    cudaGetSymbolAddress((void**)&p_pw_l, g_pw_l);

    constexpr int DD = Dq * Dq, DD4 = 4 * Dq * Dq;

    auto kB = mma_nt<128,64,4,2, 0,true ,true ,false>;  // res + f32 out
    auto kC = mma_nt<128,128,2,4, 1,false,false,true>;  // gelu + split out
    auto kD = mma_nt<128,64,4,2, 0,false,true ,false>;  // f32 out
    constexpr int SM64  = (128 + 64)  * PADK * 2 * NSTG;
    constexpr int SM128 = (128 + 128) * PADK * 2 * NSTG;
    cudaFuncSetAttribute(kB, cudaFuncAttributeMaxDynamicSharedMemorySize, SM64);
    cudaFuncSetAttribute(kC, cudaFuncAttributeMaxDynamicSharedMemorySize, SM128);
    cudaFuncSetAttribute(kD, cudaFuncAttributeMaxDynamicSharedMemorySize, SM64);

    // 1) layer-0 fold prep (transpose vw0 + cb0)
    fold_prep_k<<<dim3(16,16), 256>>>(ly_vw, ly_ow, ly_vb, ly_ob, p_vwT, p_cb);
    // 2) Wc0 = ow0 @ vw0 (fp32) -> bf16 split
    gemm_nt<0,false,true><<<dim3(8,8), 256>>>(ly_ow, p_vwT, p_zero, nullptr,
                                              p_wc_h, p_wc_l, Dq, Dq, Dq);
    // 3) fused weight splits (8 segments)
    {
        SplitArgs sa;
        int s = 0, tot = 0;
        auto add = [&](const float* src, __nv_bfloat16* h, __nv_bfloat16* l, int n) {
            sa.seg[s++] = SplitSeg{src, h, l, n}; tot += n;
        };
        for (int l = 0; l < Lq; l++) {
            add(ly_w1 + (size_t)l * DD4, p_w1_h + (size_t)l * DD4, p_w1_l + (size_t)l * DD4, DD4);
            add(ly_w2 + (size_t)l * DD4, p_w2_h + (size_t)l * DD4, p_w2_l + (size_t)l * DD4, DD4);
        }
        add(t_kw,   p_kvw_h,      p_kvw_l,      DD);
        add(t_vw,   p_kvw_h + DD, p_kvw_l + DD, DD);
        add(t_ow,   p_to_h,       p_to_l,       DD);
        add(proj_w, p_pw_h,       p_pw_l,       HLLMq * Dq);
        sa.total = tot;
        split_all_k<<<(tot + 255) / 256, 256>>>(sa);
    }
    // 4) relation projection (fp32 — feeds discrete top-k)
    gemm_nt<0,true,false><<<dim3(Dq/64, (Rq + 63)/64), 256>>>(rel_emb, rp_w, rp_b,
                                                              p_proj, nullptr, nullptr, Rq, Dq, RDq);
    // 5) sims (inline norms) + top-k + agg + states init
    sims_agg_k<<<BEq, 256>>>(edge_ids, neigh_ids);

    // 6+) relation-context layers (launch #6 = layer-0 attn GEMM -> ncu slot)
    for (int l = 0; l < Lq; l++) {
        kB<<<dim3(Dq/64, BEq/128), 256, SM64>>>(
            p_agg_h, p_agg_l, p_wc_h + (size_t)l*DD, p_wc_l + (size_t)l*DD,
            p_cb + l*Dq, p_states, p_t2, nullptr, nullptr, BEq, Dq, Dq);
        ln_k<false><<<BEq, 256>>>(p_t2, ly_n1g + l*Dq, ly_n1b + l*Dq, nullptr,
                                  p_states, p_st_h, p_st_l);

        kC<<<dim3(4*Dq/128, BEq/128), 256, SM128>>>(
            p_st_h, p_st_l, p_w1_h + (size_t)l*DD4, p_w1_l + (size_t)l*DD4,
            ly_b1 + l*4*Dq, nullptr, nullptr, p_hid_h, p_hid_l, BEq, 4*Dq, Dq);

        kB<<<dim3(Dq/64, BEq/128), 256, SM64>>>(
            p_hid_h, p_hid_l, p_w2_h + (size_t)l*DD4, p_w2_l + (size_t)l*DD4,
            ly_b2 + l*Dq, p_states, p_t2, nullptr, nullptr, BEq, Dq, 4*Dq);
        ln_k<true><<<BEq, 256>>>(p_t2, ly_n2g + l*Dq, ly_n2b + l*Dq, edge_mask,
                                 p_states, p_st_h, p_st_l);

        if (l + 1 < Lq) {   // prep next layer's folded weight
            fold_prep_k<<<dim3(16,16), 256>>>(ly_vw + (size_t)(l+1)*DD, ly_ow + (size_t)(l+1)*DD,
                                              ly_vb + (l+1)*Dq, ly_ob + (l+1)*Dq,
                                              p_vwT, p_cb + (l+1)*Dq);
            gemm_nt<0,false,true><<<dim3(8,8), 256>>>(ly_ow + (size_t)(l+1)*DD, p_vwT, p_zero,
                                                      nullptr, p_wc_h + (size_t)(l+1)*DD,
                                                      p_wc_l + (size_t)(l+1)*DD, Dq, Dq, Dq);
        }
    }

    // tokenizer projections (combined K|V in one GEMM)
    gemm_nt<0,true,false><<<dim3(Dq/64, 1), 256>>>(mem_q, t_qw, t_qb, p_q, nullptr, nullptr,
                                                   Mq, Dq, Dq);
    pack_kvb_k<<<4, 256>>>(t_kb, t_vb);
    kD<<<dim3(2*Dq/64, BEq/128), 256, SM64>>>(
        p_st_h, p_st_l, p_kvw_h, p_kvw_l, p_kvb, nullptr, p_kv, nullptr, nullptr, BEq, 2*Dq, Dq);

    // attention (head-parallel) + output proj + masking
    noedge_k<<<Bq, 256>>>(edge_mask);
    attn_k<<<Bq * Mq * Hq, 256>>>(edge_mask);
    kD<<<dim3(Dq/64, (Bq*Mq)/128), 256, SM64>>>(
        p_mem_h, p_mem_l, p_to_h, p_to_l, t_ob, nullptr, p_mem2, nullptr, nullptr, Bq*Mq, Dq, Dq);
    memmask_k<<<(Bq*Mq*Dq)/256, 256>>>();

    // LLM projection -> d_out
    kD<<<dim3(HLLMq/64, (Bq*Mq)/128), 256, SM64>>>(
        p_m2_h, p_m2_l, p_pw_h, p_pw_l, proj_b, nullptr, out, nullptr, nullptr, Bq*Mq, HLLMq, Dq);
}

// round 6
// speedup vs baseline: 1.7012x; 1.1628x over previous
#include <cuda_runtime.h>
#include <cuda_bf16.h>
#include <math.h>
#include <float.h>
#include <stdint.h>

// ---------------- problem constants ----------------
constexpr int Bq = 8, Eq = 256, Nq = 32;
constexpr int Dq = 512, RDq = 768, Rq = 2000;
constexpr int Lq = 2, Kq = 8, Mq = 32, Hq = 8, DHq = 64;
constexpr int HLLMq = 4096;
constexpr int BEq = Bq * Eq;          // 2048 edge tokens
constexpr int RPAD = 2048;            // rel rows padded to TM multiple
constexpr float EPSq = 1e-5f;

// ---------------- scratch (device globals; no allocs allowed) ----------------
__device__ float g_proj  [RPAD * Dq];
__device__ float g_states[BEq * Dq];
__device__ float g_t2    [BEq * Dq];
__device__ float g_kv    [BEq * 2 * Dq];   // [2048, 1024]: k | v
__device__ float g_kvb   [2 * Dq];
__device__ float g_q     [Mq * Dq];
__device__ float g_mem2  [Bq * Mq * Dq];
__device__ float g_noedge[Bq];
__device__ float g_vwT   [Lq][Dq * Dq];    // fp32 transpose of vw per layer
__device__ float g_cb    [Lq][Dq];         // folded attn bias
__device__ float g_zero512[Dq];            // never written: zero bias
// bf16 hi/lo split activation buffers
__device__ __align__(256) __nv_bfloat16 g_agg_h[BEq * Dq],      g_agg_l[BEq * Dq];
__device__ __align__(256) __nv_bfloat16 g_st_h [BEq * Dq],      g_st_l [BEq * Dq];
__device__ __align__(256) __nv_bfloat16 g_hid_h[BEq * 4 * Dq],  g_hid_l[BEq * 4 * Dq];
__device__ __align__(256) __nv_bfloat16 g_mem_h[Bq * Mq * Dq],  g_mem_l[Bq * Mq * Dq];
__device__ __align__(256) __nv_bfloat16 g_m2_h [Bq * Mq * Dq],  g_m2_l [Bq * Mq * Dq];
// bf16 hi/lo split weight buffers
__device__ __align__(256) __nv_bfloat16 g_emb_h[RPAD * RDq],     g_emb_l[RPAD * RDq]; // pad rows stay 0
__device__ __align__(256) __nv_bfloat16 g_rpw_h[Dq * RDq],       g_rpw_l[Dq * RDq];
__device__ __align__(256) __nv_bfloat16 g_ow_h[Lq][Dq * Dq],     g_ow_l[Lq][Dq * Dq];
__device__ __align__(256) __nv_bfloat16 g_vwT_h[Lq][Dq * Dq],    g_vwT_l[Lq][Dq * Dq];
__device__ __align__(256) __nv_bfloat16 g_wc_h[Lq][Dq * Dq],     g_wc_l[Lq][Dq * Dq];
__device__ __align__(256) __nv_bfloat16 g_w1_h[Lq][4 * Dq * Dq], g_w1_l[Lq][4 * Dq * Dq];
__device__ __align__(256) __nv_bfloat16 g_w2_h[Lq][4 * Dq * Dq], g_w2_l[Lq][4 * Dq * Dq];
__device__ __align__(256) __nv_bfloat16 g_kvw_h[2 * Dq * Dq],    g_kvw_l[2 * Dq * Dq];
__device__ __align__(256) __nv_bfloat16 g_to_h[Dq * Dq],         g_to_l[Dq * Dq];
__device__ __align__(256) __nv_bfloat16 g_pw_h[HLLMq * Dq],      g_pw_l[HLLMq * Dq];

__device__ __forceinline__ void splitw(float v, __nv_bfloat16* H, __nv_bfloat16* L, size_t i) {
    __nv_bfloat16 h = __float2bfloat16(v);
    H[i] = h;
    L[i] = __float2bfloat16(v - __bfloat162float(h));
}

__device__ __forceinline__ uint32_t smem_u32(const void* p) {
    uint32_t a;
    asm("{ .reg .u64 t; cvta.to.shared.u64 t, %1; cvt.u32.u64 %0, t; }" : "=r"(a) : "l"(p));
    return a;
}

// ---------------- reductions ----------------
__device__ __forceinline__ float warpSum(float v) {
    #pragma unroll
    for (int o = 16; o; o >>= 1) v += __shfl_xor_sync(0xffffffffu, v, o);
    return v;
}
__device__ __forceinline__ float warpMax(float v) {
    #pragma unroll
    for (int o = 16; o; o >>= 1) v = fmaxf(v, __shfl_xor_sync(0xffffffffu, v, o));
    return v;
}
__device__ __forceinline__ float blockSum(float v, float* red) {
    int lane = threadIdx.x & 31, w = threadIdx.x >> 5;
    int nw = blockDim.x >> 5;
    v = warpSum(v);
    if (lane == 0) red[w] = v;
    __syncthreads();
    if (w == 0) {
        float r = (lane < nw) ? red[lane] : 0.f;
        r = warpSum(r);
        if (lane == 0) red[0] = r;
    }
    __syncthreads();
    float out = red[0];
    __syncthreads();
    return out;
}
__device__ __forceinline__ float blockMax(float v, float* red) {
    int lane = threadIdx.x & 31, w = threadIdx.x >> 5;
    int nw = blockDim.x >> 5;
    v = warpMax(v);
    if (lane == 0) red[w] = v;
    __syncthreads();
    if (w == 0) {
        float r = (lane < nw) ? red[lane] : -FLT_MAX;
        r = warpMax(r);
        if (lane == 0) red[0] = r;
    }
    __syncthreads();
    float out = red[0];
    __syncthreads();
    return out;
}

// ---------------- mma.sync primitives ----------------
__device__ __forceinline__ void mma16816(float* d, const uint32_t* a, const uint32_t* b) {
    asm volatile("mma.sync.aligned.m16n8k16.row.col.f32.bf16.bf16.f32 "
        "{%0,%1,%2,%3}, {%4,%5,%6,%7}, {%8,%9}, {%0,%1,%2,%3};"
        : "+f"(d[0]), "+f"(d[1]), "+f"(d[2]), "+f"(d[3])
        : "r"(a[0]), "r"(a[1]), "r"(a[2]), "r"(a[3]), "r"(b[0]), "r"(b[1]));
}
__device__ __forceinline__ void ldsm4(uint32_t& r0, uint32_t& r1, uint32_t& r2, uint32_t& r3,
                                      uint32_t addr) {
    asm volatile("ldmatrix.sync.aligned.m8n8.x4.shared.b16 {%0,%1,%2,%3}, [%4];"
        : "=r"(r0), "=r"(r1), "=r"(r2), "=r"(r3) : "r"(addr));
}
__device__ __forceinline__ void cpasync16(uint32_t dst, const void* src) {
    asm volatile("cp.async.cg.shared.global [%0], [%1], 16;\n" :: "r"(dst), "l"(src) : "memory");
}

// ================= bf16x3 NT GEMM via mma.sync, BK=64, 4-stage pipeline =================
// C[M,N] = (Ah+Al)[M,K]*(Bh+Bl)[N,K]^T (terms AhBh+AhBl+AlBh) + bias (+res)(+gelu)
// M % TM == 0, N % TN == 0, K % 64 == 0, 3K/64 >= 3.
constexpr int PADK = 72;   // 64 + 8: 144-byte row stride, 16B-aligned, ldmatrix conflict-free
constexpr int NSTG = 4;

template<int TM, int TN, int WR, int WC, int ACT, bool RES, bool WF32, bool WSPLIT>
__global__ __launch_bounds__(256)
void mma_nt(const __nv_bfloat16* __restrict__ Ah, const __nv_bfloat16* __restrict__ Al,
            const __nv_bfloat16* __restrict__ Bh, const __nv_bfloat16* __restrict__ Bl,
            const float* __restrict__ bias, const float* __restrict__ res,
            float* __restrict__ Cf, __nv_bfloat16* __restrict__ Ch, __nv_bfloat16* __restrict__ Cl,
            int M, int N, int K)
{
    extern __shared__ __align__(128) __nv_bfloat16 smem[];
    constexpr int STG_E = (TM + TN) * PADK;
    constexpr int tm = TM / WR, tn = TN / WC;
    constexpr int MT = tm / 16, NT = tn / 8;

    const int tid = threadIdx.x;
    const int wid = tid >> 5, lane = tid & 31;
    const int bm = blockIdx.y * TM, bn = blockIdx.x * TN;
    const int wm = (wid / WC) * tm, wn = (wid % WC) * tn;
    const uint32_t sbase = smem_u32(smem);

    const int NI = (3 * K) / 64;

    auto load_stage = [&](int stage, int buf) {
        int c0 = stage * 64;
        int term = c0 / K;
        int kk = c0 - term * K;
        const __nv_bfloat16* As = (term < 2) ? Ah : Al;
        const __nv_bfloat16* Bs = (term == 1) ? Bl : Bh;
        uint32_t base = sbase + (uint32_t)buf * STG_E * 2;
        constexpr int CHA = TM * 8, CH = (TM + TN) * 8;
        #pragma unroll
        for (int j = 0; j < CH / 256; ++j) {
            int f = tid + 256 * j;
            if (f < CHA) {
                int row = f >> 3, ch = f & 7;
                cpasync16(base + (uint32_t)(row * PADK + ch * 8) * 2,
                          As + (size_t)(bm + row) * K + kk + ch * 8);
            } else {
                int f2 = f - CHA;
                int row = f2 >> 3, ch = f2 & 7;
                cpasync16(base + (uint32_t)(TM * PADK + row * PADK + ch * 8) * 2,
                          Bs + (size_t)(bn + row) * K + kk + ch * 8);
            }
        }
        asm volatile("cp.async.commit_group;\n" ::: "memory");
    };

    float d[MT][NT][4];
    #pragma unroll
    for (int a = 0; a < MT; a++)
        #pragma unroll
        for (int b = 0; b < NT; b++)
            #pragma unroll
            for (int c = 0; c < 4; c++) d[a][b][c] = 0.f;

    load_stage(0, 0);
    load_stage(1, 1);
    load_stage(2, 2);

    const int a_lrow = lane & 15, a_lk = (lane >> 4) * 8;
    const int bq = lane >> 3;
    const int b_lrow = (lane & 7) + ((bq >> 1) * 8);
    const int b_lk = (bq & 1) * 8;

    for (int i = 0; i < NI; ++i) {
        if (i + 3 <= NI)      asm volatile("cp.async.wait_group 2;\n" ::: "memory");
        else if (i + 2 == NI) asm volatile("cp.async.wait_group 1;\n" ::: "memory");
        else                  asm volatile("cp.async.wait_group 0;\n" ::: "memory");
        __syncthreads();

        if (i + 3 < NI) load_stage(i + 3, (i + 3) & (NSTG - 1));

        const uint32_t abase = sbase + (uint32_t)(i & (NSTG - 1)) * STG_E * 2;
        const uint32_t bbase = abase + TM * PADK * 2;

        #pragma unroll
        for (int kh = 0; kh < 4; ++kh) {
            const int kc = kh * 16;
            uint32_t afr[MT][4];
            #pragma unroll
            for (int mt = 0; mt < MT; ++mt)
                ldsm4(afr[mt][0], afr[mt][1], afr[mt][2], afr[mt][3],
                      abase + (uint32_t)((wm + mt * 16 + a_lrow) * PADK + kc + a_lk) * 2);
            uint32_t bfr[NT][2];
            #pragma unroll
            for (int nt2 = 0; nt2 < NT / 2; ++nt2) {
                uint32_t r0, r1, r2, r3;
                ldsm4(r0, r1, r2, r3,
                      bbase + (uint32_t)((wn + nt2 * 16 + b_lrow) * PADK + kc + b_lk) * 2);
                bfr[nt2 * 2][0] = r0; bfr[nt2 * 2][1] = r1;
                bfr[nt2 * 2 + 1][0] = r2; bfr[nt2 * 2 + 1][1] = r3;
            }
            #pragma unroll
            for (int mt = 0; mt < MT; ++mt)
                #pragma unroll
                for (int nt = 0; nt < NT; ++nt)
                    mma16816(d[mt][nt], afr[mt], bfr[nt]);
        }
    }

    const int erow = lane >> 2, ecol = (lane & 3) * 2;
    #pragma unroll
    for (int mt = 0; mt < MT; ++mt) {
        #pragma unroll
        for (int h = 0; h < 2; ++h) {
            const int row = bm + wm + mt * 16 + erow + h * 8;
            #pragma unroll
            for (int nt = 0; nt < NT; ++nt) {
                const int n = bn + wn + nt * 8 + ecol;
                float v0 = d[mt][nt][h * 2 + 0];
                float v1 = d[mt][nt][h * 2 + 1];
                float2 bv = *(const float2*)(bias + n);
                v0 += bv.x; v1 += bv.y;
                if (RES) {
                    float2 rv = *(const float2*)(res + (size_t)row * N + n);
                    v0 += rv.x; v1 += rv.y;
                }
                if (ACT == 1) {
                    v0 = 0.5f * v0 * (1.0f + erff(v0 * 0.70710678118654752f));
                    v1 = 0.5f * v1 * (1.0f + erff(v1 * 0.70710678118654752f));
                }
                if (WF32)
                    *(float2*)(Cf + (size_t)row * N + n) = make_float2(v0, v1);
                if (WSPLIT) {
                    __nv_bfloat16 h0 = __float2bfloat16(v0), h1 = __float2bfloat16(v1);
                    __nv_bfloat16 l0 = __float2bfloat16(v0 - __bfloat162float(h0));
                    __nv_bfloat16 l1 = __float2bfloat16(v1 - __bfloat162float(h1));
                    uint32_t hp = ((uint32_t)__bfloat16_as_ushort(h1) << 16) | __bfloat16_as_ushort(h0);
                    uint32_t lp = ((uint32_t)__bfloat16_as_ushort(l1) << 16) | __bfloat16_as_ushort(l0);
                    *(uint32_t*)(Ch + (size_t)row * N + n) = hp;
                    *(uint32_t*)(Cl + (size_t)row * N + n) = lp;
                }
            }
        }
    }
}

// ---------------- fp32 SIMT NT GEMM (q-proj only now) ----------------
template<int ACT, bool WF32, bool WSPLIT>
__global__ void gemm_nt(const float* __restrict__ A, const float* __restrict__ W,
                        const float* __restrict__ bias,
                        float* __restrict__ C, __nv_bfloat16* __restrict__ Ch,
                        __nv_bfloat16* __restrict__ Cl, int M, int N, int K)
{
    __shared__ float As[16][68];
    __shared__ float Ws[16][68];
    const int t  = threadIdx.x;
    const int bm = blockIdx.y * 64, bn = blockIdx.x * 64;
    const int lr = t >> 2, lk = (t & 3) * 4;
    const int ty = t >> 4, tx = t & 15;
    float acc[4][4] = {};

    for (int k0 = 0; k0 < K; k0 += 16) {
        int am = bm + lr;
        float4 av = make_float4(0.f, 0.f, 0.f, 0.f);
        if (am < M) av = *(const float4*)(A + (size_t)am * K + k0 + lk);
        As[lk + 0][lr] = av.x; As[lk + 1][lr] = av.y;
        As[lk + 2][lr] = av.z; As[lk + 3][lr] = av.w;
        int wn = bn + lr;
        float4 wv = make_float4(0.f, 0.f, 0.f, 0.f);
        if (wn < N) wv = *(const float4*)(W + (size_t)wn * K + k0 + lk);
        Ws[lk + 0][lr] = wv.x; Ws[lk + 1][lr] = wv.y;
        Ws[lk + 2][lr] = wv.z; Ws[lk + 3][lr] = wv.w;
        __syncthreads();
        #pragma unroll
        for (int kk = 0; kk < 16; kk++) {
            float4 a = *(const float4*)&As[kk][ty * 4];
            float4 b = *(const float4*)&Ws[kk][tx * 4];
            float av4[4] = {a.x, a.y, a.z, a.w};
            float bv4[4] = {b.x, b.y, b.z, b.w};
            #pragma unroll
            for (int i = 0; i < 4; i++)
                #pragma unroll
                for (int j = 0; j < 4; j++)
                    acc[i][j] += av4[i] * bv4[j];
        }
        __syncthreads();
    }
    #pragma unroll
    for (int i = 0; i < 4; i++) {
        int m = bm + ty * 4 + i;
        if (m >= M) continue;
        #pragma unroll
        for (int j = 0; j < 4; j++) {
            int n = bn + tx * 4 + j;
            if (n >= N) continue;
            float v = acc[i][j] + bias[n];
            if (ACT == 1) v = 0.5f * v * (1.0f + erff(v * 0.70710678118654752f));
            if (WF32) C[(size_t)m * N + n] = v;
            if (WSPLIT) splitw(v, Ch, Cl, (size_t)m * N + n);
        }
    }
}

// ---------------- fold prep: transpose vw + folded bias cb = ow@vb + ob ----------------
__global__ void fold_prep_k(const float* __restrict__ vw, const float* __restrict__ ow,
                            const float* __restrict__ vb, const float* __restrict__ ob,
                            float* __restrict__ vwT, float* __restrict__ cb)
{
    __shared__ float tile[32][33];
    const int bx = blockIdx.x, by = blockIdx.y;    // grid (16,16)
    const int t = threadIdx.x;                     // 256
    const int tx = t & 31, ty = t >> 5;            // 32 x 8
    #pragma unroll
    for (int r = 0; r < 4; r++)
        tile[ty + r * 8][tx] = vw[(size_t)(by * 32 + ty + r * 8) * Dq + bx * 32 + tx];
    __syncthreads();
    #pragma unroll
    for (int r = 0; r < 4; r++)
        vwT[(size_t)(bx * 32 + ty + r * 8) * Dq + by * 32 + tx] = tile[tx][ty + r * 8];

    if (by == 0) {
        int n = bx * 32 + (t >> 3), ks = t & 7;
        float p = 0.f;
        for (int k = ks * 64; k < ks * 64 + 64; k++) p += ow[(size_t)n * Dq + k] * vb[k];
        p += __shfl_xor_sync(0xffffffffu, p, 1);
        p += __shfl_xor_sync(0xffffffffu, p, 2);
        p += __shfl_xor_sync(0xffffffffu, p, 4);
        if (ks == 0) cb[n] = p + ob[n];
    }
}

// ---------------- fused weight split ----------------
struct SplitSeg { const float* src; __nv_bfloat16* h; __nv_bfloat16* l; int n; };
struct SplitArgs { SplitSeg seg[14]; int total; };

__global__ void split_all_k(SplitArgs a) {
    int i = blockIdx.x * 256 + threadIdx.x;
    if (i >= a.total) return;
    int idx = i, s = 0;
    while (idx >= a.seg[s].n) { idx -= a.seg[s].n; s++; }
    splitw(a.seg[s].src[idx], a.seg[s].h, a.seg[s].l, idx);
}

// ---------------- sims + inline norms + top-k + agg(split) + states init ----------------
__global__ void sims_agg_k(const int* __restrict__ eids, const int* __restrict__ nids)
{
    int be = blockIdx.x, t = threadIdx.x;
    int lane = t & 31, w = t >> 5;
    __shared__ float se[Dq];
    __shared__ float ssim[Nq];
    __shared__ int   snid[Nq];
    __shared__ int   ssel[Kq];
    __shared__ float red[32];

    int eid = eids[be];
    float sq = 0.f;
    for (int d = t; d < Dq; d += 256) {
        float x = g_proj[eid * Dq + d];
        se[d] = x;
        g_states[(size_t)be * Dq + d] = x;
        sq += x * x;
    }
    float en = fmaxf(sqrtf(blockSum(sq, red)), 1e-12f);

    for (int n = w; n < Nq; n += 8) {
        int nid = nids[be * Nq + n];
        float s = 0.f, q = 0.f;
        for (int d = lane; d < Dq; d += 32) {
            float p = g_proj[nid * Dq + d];
            s += p * se[d];
            q += p * p;
        }
        s = warpSum(s); q = warpSum(q);
        if (lane == 0) {
            snid[n] = nid;
            ssim[n] = s / (fmaxf(sqrtf(q), 1e-12f) * en);
        }
    }
    __syncthreads();

    if (w == 0) {
        float sv = ssim[lane];
        for (int it = 0; it < Kq; it++) {
            float bs = sv; int bi = lane;
            #pragma unroll
            for (int o = 16; o; o >>= 1) {
                float os = __shfl_xor_sync(0xffffffffu, bs, o);
                int   oi = __shfl_xor_sync(0xffffffffu, bi, o);
                if (os > bs || (os == bs && oi < bi)) { bs = os; bi = oi; }
            }
            if (lane == bi) sv = -FLT_MAX;
            if (lane == 0) ssel[it] = snid[bi];
        }
    }
    __syncthreads();

    for (int d = t; d < Dq; d += 256) {
        float a = 0.f;
        #pragma unroll
        for (int k2 = 0; k2 < Kq; k2++) a += g_proj[ssel[k2] * Dq + d];
        splitw(a * (1.0f / Kq), g_agg_h, g_agg_l, (size_t)be * Dq + d);
    }
}

// ---------------- layernorm -> fp32 states + hi/lo split ----------------
template<bool MASK>
__global__ void ln_k(const float* __restrict__ in, const float* __restrict__ g,
                     const float* __restrict__ b, const float* __restrict__ mask,
                     float* __restrict__ out, __nv_bfloat16* __restrict__ oh,
                     __nv_bfloat16* __restrict__ ol)
{
    int be = blockIdx.x, t = threadIdx.x;
    __shared__ float red[32];
    const float* x = in + (size_t)be * Dq;
    float v0 = x[t], v1 = x[t + 256];
    float mu = blockSum(v0 + v1, red) * (1.0f / Dq);
    float d0 = v0 - mu, d1 = v1 - mu;
    float var = blockSum(d0 * d0 + d1 * d1, red) * (1.0f / Dq);
    float r = rsqrtf(var + EPSq);
    float mk = MASK ? mask[be] : 1.0f;
    float o0 = (d0 * r * g[t      ] + b[t      ]) * mk;
    float o1 = (d1 * r * g[t + 256] + b[t + 256]) * mk;
    size_t i0 = (size_t)be * Dq + t, i1 = i0 + 256;
    out[i0] = o0; out[i1] = o1;
    splitw(o0, oh, ol, i0);
    splitw(o1, oh, ol, i1);
}

// ---------------- pack kv bias ----------------
__global__ void pack_kvb_k(const float* __restrict__ kb, const float* __restrict__ vb) {
    int i = blockIdx.x * 256 + threadIdx.x;    // 1024
    g_kvb[i] = (i < Dq) ? kb[i] : vb[i - Dq];
}

// ---------------- no-edge flags ----------------
__global__ void noedge_k(const float* __restrict__ mask) {
    int b = blockIdx.x;
    __shared__ float red[32];
    float s = blockSum(mask[b * Eq + threadIdx.x], red);
    if (threadIdx.x == 0) g_noedge[b] = (s == 0.f) ? 0.f : 1.f;
}

// ---------------- memory-token cross attention, head-parallel ----------------
__global__ void attn_k(const float* __restrict__ mask)
{
    int bmh = blockIdx.x;                    // B*M*H = 2048
    int h = bmh & 7, bm = bmh >> 3;
    int b = bm >> 5, m = bm & 31;
    int t = threadIdx.x;
    __shared__ float qh[DHq];
    __shared__ float sc[Eq];
    __shared__ float red[32];
    __shared__ float outp[4][DHq];

    if (t < DHq) qh[t] = g_q[m * Dq + h * DHq + t];
    __syncthreads();

    const float* kr = g_kv + (size_t)(b * Eq + t) * (2 * Dq) + h * DHq;
    float dot = 0.f;
    #pragma unroll
    for (int d = 0; d < DHq; d++) dot += qh[d] * kr[d];
    float s = dot * 0.125f;
    if (mask[b * Eq + t] == 0.f) s = -FLT_MAX;

    float mx = blockMax(s, red);
    float e = expf(s - mx);
    sc[t] = e;
    float sum = blockSum(e, red);

    int d = t & 63, gp = t >> 6;
    const float* vb0 = g_kv + (size_t)(b * Eq) * (2 * Dq) + Dq + h * DHq + d;
    float acc = 0.f;
    #pragma unroll 4
    for (int e2 = gp * 64; e2 < gp * 64 + 64; e2++)
        acc += sc[e2] * vb0[(size_t)e2 * (2 * Dq)];
    outp[gp][d] = acc;
    __syncthreads();
    if (t < DHq) {
        float o = (outp[0][t] + outp[1][t] + outp[2][t] + outp[3][t]) / sum;
        splitw(o, g_mem_h, g_mem_l, (size_t)bm * Dq + h * DHq + t);
    }
}

// ---------------- no-edge mask + split for final proj ----------------
__global__ void memmask_k() {
    int i = blockIdx.x * 256 + threadIdx.x;
    int b = i / (Mq * Dq);
    splitw(g_mem2[i] * g_noedge[b], g_m2_h, g_m2_l, i);
}

// ---------------- launch ----------------
extern "C" void kernel_launch(void* const* d_in, const int* in_sizes, int n_in,
                              void* d_out, int out_size)
{
    const int*   edge_ids  = (const int*)  d_in[0];
    const int*   neigh_ids = (const int*)  d_in[1];
    const float* edge_mask = (const float*)d_in[2];
    const float* rel_emb   = (const float*)d_in[3];
    const float* rp_w      = (const float*)d_in[4];
    const float* rp_b      = (const float*)d_in[5];
    const float* ly_vw     = (const float*)d_in[6];
    const float* ly_vb     = (const float*)d_in[7];
    const float* ly_ow     = (const float*)d_in[8];
    const float* ly_ob     = (const float*)d_in[9];
    const float* ly_n1g    = (const float*)d_in[10];
    const float* ly_n1b    = (const float*)d_in[11];
    const float* ly_n2g    = (const float*)d_in[12];
    const float* ly_n2b    = (const float*)d_in[13];
    const float* ly_w1     = (const float*)d_in[14];
    const float* ly_b1     = (const float*)d_in[15];
    const float* ly_w2     = (const float*)d_in[16];
    const float* ly_b2     = (const float*)d_in[17];
    const float* mem_q     = (const float*)d_in[18];
    const float* t_qw      = (const float*)d_in[19];
    const float* t_qb      = (const float*)d_in[20];
    const float* t_kw      = (const float*)d_in[21];
    const float* t_kb      = (const float*)d_in[22];
    const float* t_vw      = (const float*)d_in[23];
    const float* t_vb      = (const float*)d_in[24];
    const float* t_ow      = (const float*)d_in[25];
    const float* t_ob      = (const float*)d_in[26];
    const float* proj_w    = (const float*)d_in[27];
    const float* proj_b    = (const float*)d_in[28];
    float* out = (float*)d_out;

    float *p_proj, *p_states, *p_t2, *p_kv, *p_kvb, *p_q, *p_mem2, *p_vwT, *p_cb, *p_zero;
    cudaGetSymbolAddress((void**)&p_proj,   g_proj);
    cudaGetSymbolAddress((void**)&p_states, g_states);
    cudaGetSymbolAddress((void**)&p_t2,     g_t2);
    cudaGetSymbolAddress((void**)&p_kv,     g_kv);
    cudaGetSymbolAddress((void**)&p_kvb,    g_kvb);
    cudaGetSymbolAddress((void**)&p_q,      g_q);
    cudaGetSymbolAddress((void**)&p_mem2,   g_mem2);
    cudaGetSymbolAddress((void**)&p_vwT,    g_vwT);
    cudaGetSymbolAddress((void**)&p_cb,     g_cb);
    cudaGetSymbolAddress((void**)&p_zero,   g_zero512);

    __nv_bfloat16 *p_agg_h, *p_agg_l, *p_st_h, *p_st_l, *p_hid_h, *p_hid_l;
    __nv_bfloat16 *p_mem_h, *p_mem_l, *p_m2_h, *p_m2_l;
    cudaGetSymbolAddress((void**)&p_agg_h,  g_agg_h);
    cudaGetSymbolAddress((void**)&p_agg_l,  g_agg_l);
    cudaGetSymbolAddress((void**)&p_st_h,   g_st_h);
    cudaGetSymbolAddress((void**)&p_st_l,   g_st_l);
    cudaGetSymbolAddress((void**)&p_hid_h,  g_hid_h);
    cudaGetSymbolAddress((void**)&p_hid_l,  g_hid_l);
    cudaGetSymbolAddress((void**)&p_mem_h,  g_mem_h);
    cudaGetSymbolAddress((void**)&p_mem_l,  g_mem_l);
    cudaGetSymbolAddress((void**)&p_m2_h,   g_m2_h);
    cudaGetSymbolAddress((void**)&p_m2_l,   g_m2_l);

    __nv_bfloat16 *p_emb_h, *p_emb_l, *p_rpw_h, *p_rpw_l, *p_ow_h, *p_ow_l, *p_vwT_h, *p_vwT_l;
    __nv_bfloat16 *p_wc_h, *p_wc_l, *p_w1_h, *p_w1_l, *p_w2_h, *p_w2_l;
    __nv_bfloat16 *p_kvw_h, *p_kvw_l, *p_to_h, *p_to_l, *p_pw_h, *p_pw_l;
    cudaGetSymbolAddress((void**)&p_emb_h, g_emb_h);
    cudaGetSymbolAddress((void**)&p_emb_l, g_emb_l);
    cudaGetSymbolAddress((void**)&p_rpw_h, g_rpw_h);
    cudaGetSymbolAddress((void**)&p_rpw_l, g_rpw_l);
    cudaGetSymbolAddress((void**)&p_ow_h,  g_ow_h);
    cudaGetSymbolAddress((void**)&p_ow_l,  g_ow_l);
    cudaGetSymbolAddress((void**)&p_vwT_h, g_vwT_h);
    cudaGetSymbolAddress((void**)&p_vwT_l, g_vwT_l);
    cudaGetSymbolAddress((void**)&p_wc_h,  g_wc_h);
    cudaGetSymbolAddress((void**)&p_wc_l,  g_wc_l);
    cudaGetSymbolAddress((void**)&p_w1_h,  g_w1_h);
    cudaGetSymbolAddress((void**)&p_w1_l,  g_w1_l);
    cudaGetSymbolAddress((void**)&p_w2_h,  g_w2_h);
    cudaGetSymbolAddress((void**)&p_w2_l,  g_w2_l);
    cudaGetSymbolAddress((void**)&p_kvw_h, g_kvw_h);
    cudaGetSymbolAddress((void**)&p_kvw_l, g_kvw_l);
    cudaGetSymbolAddress((void**)&p_to_h,  g_to_h);
    cudaGetSymbolAddress((void**)&p_to_l,  g_to_l);
    cudaGetSymbolAddress((void**)&p_pw_h,  g_pw_h);
    cudaGetSymbolAddress((void**)&p_pw_l,  g_pw_l);

    constexpr int DD = Dq * Dq, DD4 = 4 * Dq * Dq;

    auto kA = mma_nt<128,64,4,2, 0,false,false,true>;   // split out (Wc)
    auto kB = mma_nt<128,64,4,2, 0,true ,true ,false>;  // res + f32 out
    auto kC = mma_nt<128,128,2,4, 1,false,false,true>;  // gelu + split out
    auto kD = mma_nt<128,64,4,2, 0,false,true ,false>;  // f32 out
    constexpr int SM64  = (128 + 64)  * PADK * 2 * NSTG;  // 110592
    constexpr int SM128 = (128 + 128) * PADK * 2 * NSTG;  // 147456
    cudaFuncSetAttribute(kA, cudaFuncAttributeMaxDynamicSharedMemorySize, SM64);
    cudaFuncSetAttribute(kB, cudaFuncAttributeMaxDynamicSharedMemorySize, SM64);
    cudaFuncSetAttribute(kC, cudaFuncAttributeMaxDynamicSharedMemorySize, SM128);
    cudaFuncSetAttribute(kD, cudaFuncAttributeMaxDynamicSharedMemorySize, SM64);

    // -- front-loaded prep --
    fold_prep_k<<<dim3(16,16), 256>>>(ly_vw, ly_ow, ly_vb, ly_ob, p_vwT, p_cb);
    fold_prep_k<<<dim3(16,16), 256>>>(ly_vw + (size_t)DD, ly_ow + (size_t)DD,
                                      ly_vb + Dq, ly_ob + Dq, p_vwT + (size_t)DD, p_cb + Dq);
    pack_kvb_k<<<4, 256>>>(t_kb, t_vb);
    noedge_k<<<Bq, 256>>>(edge_mask);
    gemm_nt<0,true,false><<<dim3(Dq/64, 1), 256>>>(mem_q, t_qw, t_qb, p_q, nullptr, nullptr,
                                                   Mq, Dq, Dq);

    // fused splits (14 segments; g_emb pad rows stay zero from static init)
    {
        SplitArgs sa;
        int s = 0, tot = 0;
        auto add = [&](const float* src, __nv_bfloat16* h, __nv_bfloat16* l, int n) {
            sa.seg[s++] = SplitSeg{src, h, l, n}; tot += n;
        };
        for (int l = 0; l < Lq; l++) {
            add(ly_w1 + (size_t)l * DD4, p_w1_h + (size_t)l * DD4, p_w1_l + (size_t)l * DD4, DD4);
            add(ly_w2 + (size_t)l * DD4, p_w2_h + (size_t)l * DD4, p_w2_l + (size_t)l * DD4, DD4);
            add(ly_ow + (size_t)l * DD,  p_ow_h + (size_t)l * DD,  p_ow_l + (size_t)l * DD,  DD);
            add(p_vwT + (size_t)l * DD,  p_vwT_h + (size_t)l * DD, p_vwT_l + (size_t)l * DD, DD);
        }
        add(t_kw,    p_kvw_h,      p_kvw_l,      DD);
        add(t_vw,    p_kvw_h + DD, p_kvw_l + DD, DD);
        add(t_ow,    p_to_h,       p_to_l,       DD);
        add(proj_w,  p_pw_h,       p_pw_l,       HLLMq * Dq);
        add(rel_emb, p_emb_h,      p_emb_l,      Rq * RDq);
        add(rp_w,    p_rpw_h,      p_rpw_l,      Dq * RDq);
        sa.total = tot;
        split_all_k<<<(tot + 255) / 256, 256>>>(sa);
    }

    // Wc = ow @ vw (bf16x3) per layer -> split
    for (int l = 0; l < Lq; l++)
        kA<<<dim3(Dq/64, Dq/128), 256, SM64>>>(
            p_ow_h + (size_t)l*DD, p_ow_l + (size_t)l*DD,
            p_vwT_h + (size_t)l*DD, p_vwT_l + (size_t)l*DD,
            p_zero, nullptr, nullptr, p_wc_h + (size_t)l*DD, p_wc_l + (size_t)l*DD, Dq, Dq, Dq);

    // relation projection (bf16x3, padded M=2048) -> fp32 proj table
    kD<<<dim3(Dq/64, RPAD/128), 256, SM64>>>(
        p_emb_h, p_emb_l, p_rpw_h, p_rpw_l, rp_b, nullptr, p_proj, nullptr, nullptr,
        RPAD, Dq, RDq);

    // sims + top-k + agg + states init
    sims_agg_k<<<BEq, 256>>>(edge_ids, neigh_ids);

    // relation-context layers
    for (int l = 0; l < Lq; l++) {
        kB<<<dim3(Dq/64, BEq/128), 256, SM64>>>(
            p_agg_h, p_agg_l, p_wc_h + (size_t)l*DD, p_wc_l + (size_t)l*DD,
            p_cb + l*Dq, p_states, p_t2, nullptr, nullptr, BEq, Dq, Dq);
        ln_k<false><<<BEq, 256>>>(p_t2, ly_n1g + l*Dq, ly_n1b + l*Dq, nullptr,
                                  p_states, p_st_h, p_st_l);

        kC<<<dim3(4*Dq/128, BEq/128), 256, SM128>>>(
            p_st_h, p_st_l, p_w1_h + (size_t)l*DD4, p_w1_l + (size_t)l*DD4,
            ly_b1 + l*4*Dq, nullptr, nullptr, p_hid_h, p_hid_l, BEq, 4*Dq, Dq);

        kB<<<dim3(Dq/64, BEq/128), 256, SM64>>>(
            p_hid_h, p_hid_l, p_w2_h + (size_t)l*DD4, p_w2_l + (size_t)l*DD4,
            ly_b2 + l*Dq, p_states, p_t2, nullptr, nullptr, BEq, Dq, 4*Dq);
        ln_k<true><<<BEq, 256>>>(p_t2, ly_n2g + l*Dq, ly_n2b + l*Dq, edge_mask,
                                 p_states, p_st_h, p_st_l);
    }

    // tokenizer K|V projection (combined)
    kD<<<dim3(2*Dq/64, BEq/128), 256, SM64>>>(
        p_st_h, p_st_l, p_kvw_h, p_kvw_l, p_kvb, nullptr, p_kv, nullptr, nullptr, BEq, 2*Dq, Dq);

    // attention + output proj + masking
    attn_k<<<Bq * Mq * Hq, 256>>>(edge_mask);
    kD<<<dim3(Dq/64, (Bq*Mq)/128), 256, SM64>>>(
        p_mem_h, p_mem_l, p_to_h, p_to_l, t_ob, nullptr, p_mem2, nullptr, nullptr, Bq*Mq, Dq, Dq);
    memmask_k<<<(Bq*Mq*Dq)/256, 256>>>();

    // LLM projection -> d_out
    kD<<<dim3(HLLMq/64, (Bq*Mq)/128), 256, SM64>>>(
        p_m2_h, p_m2_l, p_pw_h, p_pw_l, proj_b, nullptr, out, nullptr, nullptr, Bq*Mq, HLLMq, Dq);
}